// round 3
// baseline (speedup 1.0000x reference)
#include <cuda_runtime.h>
#include <cuda_bf16.h>
#include <math.h>

// ---------------- problem constants ----------------
#define BB 32
#define EMB 512
#define HID 512
#define VV 32000
#define TT 21
#define TS 20            // T-1 LSTM steps

// ---------------- device scratch ----------------
__device__ float g_act1[32*64*112*112];
__device__ float g_pool1[32*64*56*56];
__device__ float g_act2[32*128*28*28];
__device__ float g_act3[32*256*14*14];
__device__ float g_act4[32*512*7*7];
__device__ float g_feats[BB*512];
__device__ float g_enc[BB*EMB];
__device__ float g_h[2][BB*HID];
__device__ float g_c[2][BB*HID];
__device__ float g_xs[BB*TS*EMB];
__device__ float g_xpart[BB*TS*4*HID];
__device__ float g_wihT[EMB*4*HID];
__device__ float g_whhT[HID*4*HID];
__device__ float g_hs[BB*TS*HID];
__device__ float g_mean[512];
__device__ float g_rstd[512];

// ---------------- conv1: 7x7 stride2 pad3, 3->64, 224->112 ----------------
__global__ void conv7_kernel(const float* __restrict__ in, const float* __restrict__ w,
                             float* __restrict__ out) {
    __shared__ float sw[147];
    int co = blockIdx.y, n = blockIdx.z;
    if (threadIdx.x < 147) sw[threadIdx.x] = w[co*147 + threadIdx.x];
    __syncthreads();
    int p = blockIdx.x*256 + threadIdx.x;
    if (p >= 112*112) return;
    int oh = p / 112, ow = p % 112;
    float acc = 0.f;
    int iw0 = ow*2 - 3;
    for (int ci = 0; ci < 3; ci++) {
        const float* ip = in + ((long)(n*3 + ci))*224*224;
        const float* wp = sw + ci*49;
        #pragma unroll
        for (int kh = 0; kh < 7; kh++) {
            int ih = oh*2 - 3 + kh;
            if ((unsigned)ih >= 224u) continue;
            const float* row = ip + ih*224;
            const float* wr = wp + kh*7;
            #pragma unroll
            for (int kw = 0; kw < 7; kw++) {
                int iw = iw0 + kw;
                if ((unsigned)iw < 224u) acc += row[iw]*wr[kw];
            }
        }
    }
    out[(((long)n*64 + co)*112 + oh)*112 + ow] = acc;
}

// ---------------- generic 3x3 stride2 pad1 conv ----------------
__global__ void conv3_kernel(const float* __restrict__ in, const float* __restrict__ w,
                             float* __restrict__ out, int Cin, int Cout, int Hin, int Hout) {
    extern __shared__ float sw[];
    int co = blockIdx.y, n = blockIdx.z;
    int wcnt = Cin*9;
    for (int i = threadIdx.x; i < wcnt; i += blockDim.x) sw[i] = w[(long)co*wcnt + i];
    __syncthreads();
    int p = blockIdx.x*blockDim.x + threadIdx.x;
    int HW = Hout*Hout;
    if (p >= HW) return;
    int oh = p / Hout, ow = p % Hout;
    int ih0 = oh*2 - 1, iw0 = ow*2 - 1;
    float acc = 0.f;
    for (int ci = 0; ci < Cin; ci++) {
        const float* ip = in + ((long)(n*Cin + ci))*Hin*Hin;
        const float* wp = sw + ci*9;
        #pragma unroll
        for (int kh = 0; kh < 3; kh++) {
            int ih = ih0 + kh;
            if ((unsigned)ih >= (unsigned)Hin) continue;
            const float* row = ip + ih*Hin;
            const float* wr = wp + kh*3;
            #pragma unroll
            for (int kw = 0; kw < 3; kw++) {
                int iw = iw0 + kw;
                if ((unsigned)iw < (unsigned)Hin) acc += row[iw]*wr[kw];
            }
        }
    }
    out[(((long)n*Cout + co)*Hout + oh)*Hout + ow] = acc;
}

// ---------------- BN stats: one block per channel ----------------
__global__ void bn_stats_kernel(const float* __restrict__ x, float* __restrict__ mean,
                                float* __restrict__ rstd, int N, int C, int HW) {
    int c = blockIdx.x;
    float s = 0.f, s2 = 0.f;
    for (int n = 0; n < N; n++) {
        const float* p = x + ((long)n*C + c)*HW;
        for (int i = threadIdx.x; i < HW; i += blockDim.x) {
            float v = p[i];
            s += v; s2 += v*v;
        }
    }
    __shared__ float ss[256], ss2[256];
    ss[threadIdx.x] = s; ss2[threadIdx.x] = s2;
    __syncthreads();
    for (int o = 128; o > 0; o >>= 1) {
        if (threadIdx.x < o) { ss[threadIdx.x] += ss[threadIdx.x+o]; ss2[threadIdx.x] += ss2[threadIdx.x+o]; }
        __syncthreads();
    }
    if (threadIdx.x == 0) {
        float inv = 1.f / ((float)N * (float)HW);
        float m = ss[0]*inv;
        float var = ss2[0]*inv - m*m;
        mean[c] = m;
        rstd[c] = rsqrtf(var + 1e-5f);
    }
}

// ---------------- BN apply + ReLU (in-place ok, grid-stride) ----------------
__global__ void bn_apply_kernel(const float* __restrict__ x, float* __restrict__ y,
                                const float* __restrict__ mean, const float* __restrict__ rstd,
                                const float* __restrict__ g, const float* __restrict__ b,
                                int C, int HW, long total) {
    long stride = (long)gridDim.x * blockDim.x;
    for (long i = (long)blockIdx.x*blockDim.x + threadIdx.x; i < total; i += stride) {
        int c = (int)((i / HW) % C);
        float v = (x[i] - mean[c]) * rstd[c] * g[c] + b[c];
        y[i] = v > 0.f ? v : 0.f;
    }
}

// ---------------- maxpool 3x3 s2 p1, 112->56 ----------------
__global__ void maxpool_kernel(const float* __restrict__ x, float* __restrict__ y) {
    int idx = blockIdx.x*blockDim.x + threadIdx.x;
    const int total = 32*64*56*56;
    if (idx >= total) return;
    int ow = idx % 56, oh = (idx/56) % 56;
    long nc = idx / (56*56);
    const float* p = x + nc*112*112;
    float m = -INFINITY;
    #pragma unroll
    for (int kh = 0; kh < 3; kh++) {
        int ih = oh*2 - 1 + kh;
        if ((unsigned)ih >= 112u) continue;
        #pragma unroll
        for (int kw = 0; kw < 3; kw++) {
            int iw = ow*2 - 1 + kw;
            if ((unsigned)iw >= 112u) continue;
            float v = p[ih*112 + iw];
            m = v > m ? v : m;
        }
    }
    y[idx] = m;
}

// ---------------- global avg pool 7x7 ----------------
__global__ void avgpool_kernel(const float* __restrict__ x, float* __restrict__ y) {
    int idx = blockIdx.x*blockDim.x + threadIdx.x;
    if (idx >= BB*512) return;
    const float* p = x + (long)idx*49;
    float s = 0.f;
    #pragma unroll
    for (int i = 0; i < 49; i++) s += p[i];
    y[idx] = s * (1.f/49.f);
}

// ---------------- small FC: out[M,N] = A[M,K] @ B[K,N] + bias (opt tanh) ----------------
__global__ void fc_kernel(const float* __restrict__ A, const float* __restrict__ Bm,
                          const float* __restrict__ bias, float* __restrict__ out,
                          int M, int N, int K, int act) {
    int idx = blockIdx.x*blockDim.x + threadIdx.x;
    if (idx >= M*N) return;
    int m = idx / N, n = idx % N;
    float acc = bias ? bias[n] : 0.f;
    const float* a = A + (long)m*K;
    for (int k = 0; k < K; k++) acc += a[k] * Bm[(long)k*N + n];
    if (act) acc = tanhf(acc);
    out[idx] = acc;
}

// ---------------- transpose [R,C] -> [C,R] ----------------
__global__ void transpose_kernel(const float* __restrict__ a, float* __restrict__ at,
                                 int R, int C) {
    __shared__ float tile[32][33];
    int r = blockIdx.y*32 + threadIdx.y;
    int c = blockIdx.x*32 + threadIdx.x;
    if (r < R && c < C) tile[threadIdx.y][threadIdx.x] = a[(long)r*C + c];
    __syncthreads();
    int r2 = blockIdx.x*32 + threadIdx.y;
    int c2 = blockIdx.y*32 + threadIdx.x;
    if (r2 < C && c2 < R) at[(long)r2*R + c2] = tile[threadIdx.x][threadIdx.y];
}

// ---------------- embedding gather: xs[b*20+t][e] = emb[captions[b*21+t]][e] ----------------
__global__ void embed_kernel(const int* __restrict__ captions, const float* __restrict__ emb,
                             float* __restrict__ xs) {
    int idx = blockIdx.x*blockDim.x + threadIdx.x;
    if (idx >= BB*TS*EMB) return;
    int e = idx % EMB;
    int r = idx / EMB;
    int b = r / TS, t = r % TS;
    int tok = captions[b*TT + t];
    xs[idx] = emb[(long)tok*EMB + e];
}

// ---------------- tiled SGEMM: C[M,N] = A[M,K]@B[K,N] + bias1 + bias2 ----------------
// BM=BN=64, BK=16, 256 threads, 4x4 per thread. M,N multiples of 64; K multiple of 16.
__global__ void sgemm_bias_kernel(const float* __restrict__ A, const float* __restrict__ B,
                                  const float* __restrict__ bias1, const float* __restrict__ bias2,
                                  float* __restrict__ C, int M, int N, int K) {
    __shared__ float As[16][64];
    __shared__ float Bs[16][64];
    int tid = threadIdx.x;
    int tx = tid & 15, ty = tid >> 4;
    int row0 = blockIdx.y*64, col0 = blockIdx.x*64;
    const float* Ab = A + (long)row0*K;
    const float* Bb = B + col0;
    float acc[4][4] = {};
    int am = tid >> 2;          // 0..63
    int ak = (tid & 3) * 4;     // 0,4,8,12
    int bk = tid >> 4;          // 0..15
    int bn = (tid & 15) * 4;    // 0..60
    for (int k0 = 0; k0 < K; k0 += 16) {
        float4 av = *(const float4*)(Ab + (long)am*K + k0 + ak);
        As[ak  ][am] = av.x;
        As[ak+1][am] = av.y;
        As[ak+2][am] = av.z;
        As[ak+3][am] = av.w;
        float4 bv = *(const float4*)(Bb + (long)(k0 + bk)*N + bn);
        *(float4*)&Bs[bk][bn] = bv;
        __syncthreads();
        #pragma unroll
        for (int k = 0; k < 16; k++) {
            float ar[4], br[4];
            #pragma unroll
            for (int i = 0; i < 4; i++) ar[i] = As[k][ty*4 + i];
            #pragma unroll
            for (int j = 0; j < 4; j++) br[j] = Bs[k][tx*4 + j];
            #pragma unroll
            for (int i = 0; i < 4; i++)
                #pragma unroll
                for (int j = 0; j < 4; j++) acc[i][j] += ar[i]*br[j];
        }
        __syncthreads();
    }
    #pragma unroll
    for (int i = 0; i < 4; i++) {
        long r = row0 + ty*4 + i;
        #pragma unroll
        for (int j = 0; j < 4; j++) {
            int c = col0 + tx*4 + j;
            float v = acc[i][j];
            if (bias1) v += bias1[c];
            if (bias2) v += bias2[c];
            C[r*N + c] = v;
        }
    }
}

// ---------------- LSTM step: gates = xpart + h @ whhT; cell update ----------------
// grid (4, 32), 128 threads: j = bx*128+tx in [0,512), b = by
__global__ void lstm_step_kernel(const float* __restrict__ xpart, const float* __restrict__ whhT,
                                 const float* __restrict__ h_in, const float* __restrict__ c_in,
                                 float* __restrict__ h_out, float* __restrict__ c_out,
                                 float* __restrict__ hs, int t) {
    int b = blockIdx.y;
    int j = blockIdx.x*blockDim.x + threadIdx.x;
    __shared__ float sh[HID];
    for (int k = threadIdx.x; k < HID; k += blockDim.x) sh[k] = h_in[b*HID + k];
    __syncthreads();
    const float* xp = xpart + (long)(b*TS + t)*4*HID;
    float gi = xp[j], gf = xp[HID + j], gg = xp[2*HID + j], go = xp[3*HID + j];
    for (int k = 0; k < HID; k++) {
        float hv = sh[k];
        const float* wr = whhT + (long)k*4*HID;
        gi += hv * wr[j];
        gf += hv * wr[HID + j];
        gg += hv * wr[2*HID + j];
        go += hv * wr[3*HID + j];
    }
    float si = 1.f/(1.f + expf(-gi));
    float sf = 1.f/(1.f + expf(-gf));
    float tg = tanhf(gg);
    float so = 1.f/(1.f + expf(-go));
    float cn = sf * c_in[b*HID + j] + si * tg;
    float hn = so * tanhf(cn);
    c_out[b*HID + j] = cn;
    h_out[b*HID + j] = hn;
    hs[(long)(b*TS + t)*HID + j] = hn;
}

// ---------------- host launch ----------------
extern "C" void kernel_launch(void* const* d_in, const int* in_sizes, int n_in,
                              void* d_out, int out_size) {
    const float* images   = (const float*)d_in[0];
    const int*   captions = (const int*)  d_in[1];
    const float* w1  = (const float*)d_in[2];
    const float* g1  = (const float*)d_in[3];
    const float* be1 = (const float*)d_in[4];
    const float* w2  = (const float*)d_in[5];
    const float* g2  = (const float*)d_in[6];
    const float* be2 = (const float*)d_in[7];
    const float* w3  = (const float*)d_in[8];
    const float* g3  = (const float*)d_in[9];
    const float* be3 = (const float*)d_in[10];
    const float* w4  = (const float*)d_in[11];
    const float* g4  = (const float*)d_in[12];
    const float* be4 = (const float*)d_in[13];
    const float* pw  = (const float*)d_in[14];
    const float* pb  = (const float*)d_in[15];
    const float* emb = (const float*)d_in[16];
    const float* ihw = (const float*)d_in[17];
    const float* ihb = (const float*)d_in[18];
    const float* icw = (const float*)d_in[19];
    const float* icb = (const float*)d_in[20];
    const float* wih = (const float*)d_in[21];
    const float* whh = (const float*)d_in[22];
    const float* bih = (const float*)d_in[23];
    const float* bhh = (const float*)d_in[24];
    const float* ow  = (const float*)d_in[25];
    const float* ob  = (const float*)d_in[26];
    float* out = (float*)d_out;

    float *act1, *pool1, *act2, *act3, *act4, *feats, *enc, *xs, *xpart;
    float *wihT, *whhT, *hs, *mean, *rstd, *h0, *h1, *c0, *c1;
    cudaGetSymbolAddress((void**)&act1,  g_act1);
    cudaGetSymbolAddress((void**)&pool1, g_pool1);
    cudaGetSymbolAddress((void**)&act2,  g_act2);
    cudaGetSymbolAddress((void**)&act3,  g_act3);
    cudaGetSymbolAddress((void**)&act4,  g_act4);
    cudaGetSymbolAddress((void**)&feats, g_feats);
    cudaGetSymbolAddress((void**)&enc,   g_enc);
    cudaGetSymbolAddress((void**)&xs,    g_xs);
    cudaGetSymbolAddress((void**)&xpart, g_xpart);
    cudaGetSymbolAddress((void**)&wihT,  g_wihT);
    cudaGetSymbolAddress((void**)&whhT,  g_whhT);
    cudaGetSymbolAddress((void**)&hs,    g_hs);
    cudaGetSymbolAddress((void**)&mean,  g_mean);
    cudaGetSymbolAddress((void**)&rstd,  g_rstd);
    cudaGetSymbolAddress((void**)&h0,    g_h);
    cudaGetSymbolAddress((void**)&c0,    g_c);
    h1 = h0 + BB*HID;
    c1 = c0 + BB*HID;

    // ---- CNN encoder ----
    conv7_kernel<<<dim3(49, 64, 32), 256>>>(images, w1, act1);
    bn_stats_kernel<<<64, 256>>>(act1, mean, rstd, 32, 64, 112*112);
    bn_apply_kernel<<<8192, 256>>>(act1, act1, mean, rstd, g1, be1, 64, 112*112, 32L*64*112*112);
    maxpool_kernel<<<(32*64*56*56 + 255)/256, 256>>>(act1, pool1);

    conv3_kernel<<<dim3(4, 128, 32), 256, 64*9*4>>>(pool1, w2, act2, 64, 128, 56, 28);
    bn_stats_kernel<<<128, 256>>>(act2, mean, rstd, 32, 128, 784);
    bn_apply_kernel<<<8192, 256>>>(act2, act2, mean, rstd, g2, be2, 128, 784, 32L*128*784);

    conv3_kernel<<<dim3(1, 256, 32), 256, 128*9*4>>>(act2, w3, act3, 128, 256, 28, 14);
    bn_stats_kernel<<<256, 256>>>(act3, mean, rstd, 32, 256, 196);
    bn_apply_kernel<<<4096, 256>>>(act3, act3, mean, rstd, g3, be3, 256, 196, 32L*256*196);

    conv3_kernel<<<dim3(1, 512, 32), 256, 256*9*4>>>(act3, w4, act4, 256, 512, 14, 7);
    bn_stats_kernel<<<512, 256>>>(act4, mean, rstd, 32, 512, 49);
    bn_apply_kernel<<<2048, 256>>>(act4, act4, mean, rstd, g4, be4, 512, 49, 32L*512*49);

    avgpool_kernel<<<64, 256>>>(act4, feats);

    // ---- encoder -> LSTM init ----
    fc_kernel<<<64, 256>>>(feats, pw, pb, enc, BB, EMB, 512, 0);
    fc_kernel<<<64, 256>>>(enc, ihw, ihb, h0, BB, HID, EMB, 1);
    fc_kernel<<<64, 256>>>(enc, icw, icb, c0, BB, HID, EMB, 1);

    // ---- weight transposes ----
    transpose_kernel<<<dim3(512/32, 2048/32), dim3(32, 32)>>>(wih, wihT, 4*HID, EMB);
    transpose_kernel<<<dim3(512/32, 2048/32), dim3(32, 32)>>>(whh, whhT, 4*HID, HID);

    // ---- embedding + input projection (both biases folded in) ----
    embed_kernel<<<(BB*TS*EMB + 255)/256, 256>>>(captions, emb, xs);
    sgemm_bias_kernel<<<dim3(2048/64, 640/64), 256>>>(xs, wihT, bih, bhh, xpart, 640, 2048, 512);

    // ---- LSTM scan ----
    float* hbuf[2] = { h0, h1 };
    float* cbuf[2] = { c0, c1 };
    for (int t = 0; t < TS; t++) {
        lstm_step_kernel<<<dim3(4, 32), 128>>>(xpart, whhT,
                                               hbuf[t & 1], cbuf[t & 1],
                                               hbuf[(t+1) & 1], cbuf[(t+1) & 1],
                                               hs, t);
    }

    // ---- output projection ----
    sgemm_bias_kernel<<<dim3(32000/64, 640/64), 256>>>(hs, ow, ob, nullptr, out, 640, 32000, 512);
}

// round 4
// speedup vs baseline: 2.9257x; 2.9257x over previous
#include <cuda_runtime.h>
#include <cuda_bf16.h>
#include <math.h>

// ---------------- problem constants ----------------
#define BB 32
#define EMB 512
#define HID 512
#define VV 32000
#define TT 21
#define TS 20            // T-1 LSTM steps

// ---------------- device scratch ----------------
__device__ float g_col[160*401408];        // im2col buffer (max: conv1) ~257MB
__device__ float g_act1[32*64*112*112];
__device__ float g_pool1[32*64*56*56];
__device__ float g_act2[32*128*28*28];
__device__ float g_act3[32*256*14*14];
__device__ float g_act4[32*512*7*7];
__device__ float g_w1p[64*160];
__device__ float g_part1[512*32];
__device__ float g_part2[512*32];
__device__ float g_bna[512];
__device__ float g_bnb[512];
__device__ float g_feats[BB*512];
__device__ float g_enc[BB*EMB];
__device__ float g_h[2][BB*HID];
__device__ float g_c[2][BB*HID];
__device__ float g_xs[BB*TS*EMB];
__device__ float g_xpart[BB*TS*4*HID];
__device__ float g_wihT[EMB*4*HID];
__device__ float g_whhT[HID*4*HID];
__device__ float g_hs[BB*TS*HID];

// ---------------- pad conv1 weights [64,147] -> [64,160] ----------------
__global__ void padw1_kernel(const float* __restrict__ w, float* __restrict__ wp) {
    int idx = blockIdx.x*blockDim.x + threadIdx.x;
    if (idx >= 64*160) return;
    int co = idx / 160, k = idx % 160;
    wp[idx] = (k < 147) ? w[co*147 + k] : 0.f;
}

// ---------------- im2col for conv1: 7x7 s2 p3, 3ch, 224->112, K padded to 160 ----------------
__global__ void im2col7_kernel(const float* __restrict__ in, float* __restrict__ Bm) {
    int idx = blockIdx.x*blockDim.x + threadIdx.x;
    const int Npad = 401408;          // 32*112*112
    if (idx >= 160*Npad) return;
    int k = idx / Npad, col = idx - k*Npad;
    float v = 0.f;
    if (k < 147) {
        int ci = k / 49, r = k - ci*49;
        int kh = r / 7, kw = r - kh*7;
        int n = col / 12544, hw = col - n*12544;
        int oh = hw / 112, ow = hw - oh*112;
        int ih = oh*2 - 3 + kh, iw = ow*2 - 3 + kw;
        if ((unsigned)ih < 224u && (unsigned)iw < 224u)
            v = in[((long)(n*3 + ci)*224 + ih)*224 + iw];
    }
    Bm[idx] = v;
}

// ---------------- im2col for 3x3 s2 p1 conv, optional fused BN+ReLU on input ----------------
__global__ void im2col3_kernel(const float* __restrict__ in, float* __restrict__ Bm,
                               const float* __restrict__ a, const float* __restrict__ bsh,
                               int Cin, int Hin, int Wout, int HW, int Npad, int Ntrue, int total) {
    int idx = blockIdx.x*blockDim.x + threadIdx.x;
    if (idx >= total) return;
    int k = idx / Npad, col = idx - k*Npad;
    float v = 0.f;
    if (col < Ntrue) {
        int ci = k / 9, r = k - ci*9;
        int kh = r / 3, kw = r - kh*3;
        int n = col / HW, hw = col - n*HW;
        int oh = hw / Wout, ow = hw - oh*Wout;
        int ih = oh*2 - 1 + kh, iw = ow*2 - 1 + kw;
        if ((unsigned)ih < (unsigned)Hin && (unsigned)iw < (unsigned)Hin) {
            float x = in[((long)(n*Cin + ci)*Hin + ih)*Hin + iw];
            if (a) { x = a[ci]*x + bsh[ci]; x = x > 0.f ? x : 0.f; }
            v = x;
        }
    }
    Bm[idx] = v;
}

// ---------------- conv GEMM: C[co][col] = W[co][:]@B[:][col], scatter to NCHW ----------------
// 64x64x16 tiles, 256 threads, 4x4/thread. M mult 64, Npad mult 64, K mult 16.
__global__ void convgemm_kernel(const float* __restrict__ A, const float* __restrict__ B,
                                float* __restrict__ out, int M, int Npad, int K,
                                int Ntrue, int HW, int Cout) {
    __shared__ float As[16][64];
    __shared__ float Bs[16][64];
    int tid = threadIdx.x;
    int tx = tid & 15, ty = tid >> 4;
    int row0 = blockIdx.y*64, col0 = blockIdx.x*64;
    float acc[4][4] = {};
    int am = tid >> 2;
    int ak = (tid & 3) * 4;
    int bk = tid >> 4;
    int bn = (tid & 15) * 4;
    for (int k0 = 0; k0 < K; k0 += 16) {
        float4 av = *(const float4*)(A + (long)(row0 + am)*K + k0 + ak);
        As[ak  ][am] = av.x;
        As[ak+1][am] = av.y;
        As[ak+2][am] = av.z;
        As[ak+3][am] = av.w;
        float4 bv = *(const float4*)(B + (long)(k0 + bk)*Npad + col0 + bn);
        *(float4*)&Bs[bk][bn] = bv;
        __syncthreads();
        #pragma unroll
        for (int k = 0; k < 16; k++) {
            float ar[4], br[4];
            #pragma unroll
            for (int i = 0; i < 4; i++) ar[i] = As[k][ty*4 + i];
            #pragma unroll
            for (int j = 0; j < 4; j++) br[j] = Bs[k][tx*4 + j];
            #pragma unroll
            for (int i = 0; i < 4; i++)
                #pragma unroll
                for (int j = 0; j < 4; j++) acc[i][j] += ar[i]*br[j];
        }
        __syncthreads();
    }
    #pragma unroll
    for (int i = 0; i < 4; i++) {
        int co = row0 + ty*4 + i;
        #pragma unroll
        for (int j = 0; j < 4; j++) {
            int col = col0 + tx*4 + j;
            if (col < Ntrue) {
                int n = col / HW, hw = col - n*HW;
                out[((long)(n*Cout + co))*HW + hw] = acc[i][j];
            }
        }
    }
}

// ---------------- BN partial stats (deterministic, no atomics) ----------------
// grid (C, S): block (c,s) sums n = s, s+S, ... ; writes part[c*S+s]
__global__ void bn_stats_part_kernel(const float* __restrict__ x, float* __restrict__ part1,
                                     float* __restrict__ part2, int N, int C, int HW, int S) {
    int c = blockIdx.x, s0 = blockIdx.y;
    float s = 0.f, s2 = 0.f;
    for (int n = s0; n < N; n += S) {
        const float* p = x + ((long)n*C + c)*HW;
        for (int i = threadIdx.x; i < HW; i += blockDim.x) {
            float v = p[i];
            s += v; s2 += v*v;
        }
    }
    __shared__ float ss[256], ss2[256];
    ss[threadIdx.x] = s; ss2[threadIdx.x] = s2;
    __syncthreads();
    for (int o = 128; o > 0; o >>= 1) {
        if (threadIdx.x < o) { ss[threadIdx.x] += ss[threadIdx.x+o]; ss2[threadIdx.x] += ss2[threadIdx.x+o]; }
        __syncthreads();
    }
    if (threadIdx.x == 0) {
        part1[c*S + s0] = ss[0];
        part2[c*S + s0] = ss2[0];
    }
}

// ---------------- BN finalize: a = g*rstd, b = be - mean*a ----------------
__global__ void bn_finalize_kernel(const float* __restrict__ part1, const float* __restrict__ part2,
                                   const float* __restrict__ g, const float* __restrict__ be,
                                   float* __restrict__ a, float* __restrict__ bsh,
                                   int C, int S, float invcnt) {
    int c = blockIdx.x*blockDim.x + threadIdx.x;
    if (c >= C) return;
    float s = 0.f, s2 = 0.f;
    for (int i = 0; i < S; i++) { s += part1[c*S + i]; s2 += part2[c*S + i]; }
    float m = s*invcnt;
    float var = s2*invcnt - m*m;
    float r = rsqrtf(var + 1e-5f);
    float av = g[c]*r;
    a[c] = av;
    bsh[c] = be[c] - m*av;
}

// ---------------- fused BN + maxpool 3x3 s2 p1 + ReLU, 112->56 ----------------
__global__ void maxpool_bn_kernel(const float* __restrict__ x, float* __restrict__ y,
                                  const float* __restrict__ a, const float* __restrict__ bsh) {
    int idx = blockIdx.x*blockDim.x + threadIdx.x;
    const int total = 32*64*56*56;
    if (idx >= total) return;
    int ow = idx % 56, oh = (idx/56) % 56;
    int nc = idx / (56*56);
    int c = nc % 64;
    float ac = a[c], bc = bsh[c];
    const float* p = x + (long)nc*112*112;
    float m = -INFINITY;
    #pragma unroll
    for (int kh = 0; kh < 3; kh++) {
        int ih = oh*2 - 1 + kh;
        if ((unsigned)ih >= 112u) continue;
        #pragma unroll
        for (int kw = 0; kw < 3; kw++) {
            int iw = ow*2 - 1 + kw;
            if ((unsigned)iw >= 112u) continue;
            float v = ac*p[ih*112 + iw] + bc;
            m = v > m ? v : m;
        }
    }
    y[idx] = m > 0.f ? m : 0.f;
}

// ---------------- fused BN + ReLU + global avg pool 7x7 ----------------
__global__ void avgpool_bn_kernel(const float* __restrict__ x, float* __restrict__ y,
                                  const float* __restrict__ a, const float* __restrict__ bsh) {
    int idx = blockIdx.x*blockDim.x + threadIdx.x;
    if (idx >= BB*512) return;
    int c = idx % 512;
    float ac = a[c], bc = bsh[c];
    const float* p = x + (long)idx*49;
    float s = 0.f;
    #pragma unroll
    for (int i = 0; i < 49; i++) {
        float v = ac*p[i] + bc;
        s += v > 0.f ? v : 0.f;
    }
    y[idx] = s * (1.f/49.f);
}

// ---------------- small FC: out[M,N] = A[M,K] @ B[K,N] + bias (opt tanh) ----------------
__global__ void fc_kernel(const float* __restrict__ A, const float* __restrict__ Bm,
                          const float* __restrict__ bias, float* __restrict__ out,
                          int M, int N, int K, int act) {
    int idx = blockIdx.x*blockDim.x + threadIdx.x;
    if (idx >= M*N) return;
    int m = idx / N, n = idx % N;
    float acc = bias ? bias[n] : 0.f;
    const float* a = A + (long)m*K;
    for (int k = 0; k < K; k++) acc += a[k] * Bm[(long)k*N + n];
    if (act) acc = tanhf(acc);
    out[idx] = acc;
}

// ---------------- transpose [R,C] -> [C,R] ----------------
__global__ void transpose_kernel(const float* __restrict__ a, float* __restrict__ at,
                                 int R, int C) {
    __shared__ float tile[32][33];
    int r = blockIdx.y*32 + threadIdx.y;
    int c = blockIdx.x*32 + threadIdx.x;
    if (r < R && c < C) tile[threadIdx.y][threadIdx.x] = a[(long)r*C + c];
    __syncthreads();
    int r2 = blockIdx.x*32 + threadIdx.y;
    int c2 = blockIdx.y*32 + threadIdx.x;
    if (r2 < C && c2 < R) at[(long)r2*R + c2] = tile[threadIdx.x][threadIdx.y];
}

// ---------------- embedding gather ----------------
__global__ void embed_kernel(const int* __restrict__ captions, const float* __restrict__ emb,
                             float* __restrict__ xs) {
    int idx = blockIdx.x*blockDim.x + threadIdx.x;
    if (idx >= BB*TS*EMB) return;
    int e = idx % EMB;
    int r = idx / EMB;
    int b = r / TS, t = r % TS;
    int tok = captions[b*TT + t];
    xs[idx] = emb[(long)tok*EMB + e];
}

// ---------------- 64x64 SGEMM with dual bias (xpart) ----------------
__global__ void sgemm_bias_kernel(const float* __restrict__ A, const float* __restrict__ B,
                                  const float* __restrict__ bias1, const float* __restrict__ bias2,
                                  float* __restrict__ C, int M, int N, int K) {
    __shared__ float As[16][64];
    __shared__ float Bs[16][64];
    int tid = threadIdx.x;
    int tx = tid & 15, ty = tid >> 4;
    int row0 = blockIdx.y*64, col0 = blockIdx.x*64;
    float acc[4][4] = {};
    int am = tid >> 2;
    int ak = (tid & 3) * 4;
    int bk = tid >> 4;
    int bn = (tid & 15) * 4;
    for (int k0 = 0; k0 < K; k0 += 16) {
        float4 av = *(const float4*)(A + (long)(row0 + am)*K + k0 + ak);
        As[ak  ][am] = av.x;
        As[ak+1][am] = av.y;
        As[ak+2][am] = av.z;
        As[ak+3][am] = av.w;
        float4 bv = *(const float4*)(B + (long)(k0 + bk)*N + col0 + bn);
        *(float4*)&Bs[bk][bn] = bv;
        __syncthreads();
        #pragma unroll
        for (int k = 0; k < 16; k++) {
            float ar[4], br[4];
            #pragma unroll
            for (int i = 0; i < 4; i++) ar[i] = As[k][ty*4 + i];
            #pragma unroll
            for (int j = 0; j < 4; j++) br[j] = Bs[k][tx*4 + j];
            #pragma unroll
            for (int i = 0; i < 4; i++)
                #pragma unroll
                for (int j = 0; j < 4; j++) acc[i][j] += ar[i]*br[j];
        }
        __syncthreads();
    }
    #pragma unroll
    for (int i = 0; i < 4; i++) {
        long r = row0 + ty*4 + i;
        #pragma unroll
        for (int j = 0; j < 4; j++) {
            int c = col0 + tx*4 + j;
            float v = acc[i][j];
            if (bias1) v += bias1[c];
            if (bias2) v += bias2[c];
            C[r*N + c] = v;
        }
    }
}

// ---------------- 128x128x16 SGEMM + bias (logits): 256 thr, 8x8/thread ----------------
__global__ void sgemm128_kernel(const float* __restrict__ A, const float* __restrict__ B,
                                const float* __restrict__ bias, float* __restrict__ C,
                                int M, int N, int K) {
    __shared__ float As[16][128];
    __shared__ float Bs[16][128];
    int tid = threadIdx.x;
    int ty = tid >> 4, tx = tid & 15;        // 16x16 thread grid
    int row0 = blockIdx.y*128, col0 = blockIdx.x*128;
    float acc[8][8] = {};
    int ar_ = tid >> 2;                      // 0..63 (A row within tile, +64 second pass)
    int ak4 = (tid & 3) * 4;                 // 0,4,8,12
    int bk_ = tid >> 5;                      // 0..7  (B k-row, +8 second pass)
    int bn4 = (tid & 31) * 4;                // 0..124
    for (int k0 = 0; k0 < K; k0 += 16) {
        float4 a0 = *(const float4*)(A + (long)(row0 + ar_      )*K + k0 + ak4);
        float4 a1 = *(const float4*)(A + (long)(row0 + ar_ + 64 )*K + k0 + ak4);
        As[ak4  ][ar_] = a0.x; As[ak4+1][ar_] = a0.y;
        As[ak4+2][ar_] = a0.z; As[ak4+3][ar_] = a0.w;
        As[ak4  ][ar_+64] = a1.x; As[ak4+1][ar_+64] = a1.y;
        As[ak4+2][ar_+64] = a1.z; As[ak4+3][ar_+64] = a1.w;
        float4 b0 = *(const float4*)(B + (long)(k0 + bk_    )*N + col0 + bn4);
        float4 b1 = *(const float4*)(B + (long)(k0 + bk_ + 8)*N + col0 + bn4);
        *(float4*)&Bs[bk_    ][bn4] = b0;
        *(float4*)&Bs[bk_ + 8][bn4] = b1;
        __syncthreads();
        #pragma unroll
        for (int k = 0; k < 16; k++) {
            float ar[8], br[8];
            *(float4*)(ar)   = *(const float4*)&As[k][ty*8];
            *(float4*)(ar+4) = *(const float4*)&As[k][ty*8 + 4];
            *(float4*)(br)   = *(const float4*)&Bs[k][tx*8];
            *(float4*)(br+4) = *(const float4*)&Bs[k][tx*8 + 4];
            #pragma unroll
            for (int i = 0; i < 8; i++)
                #pragma unroll
                for (int j = 0; j < 8; j++) acc[i][j] += ar[i]*br[j];
        }
        __syncthreads();
    }
    #pragma unroll
    for (int i = 0; i < 8; i++) {
        long r = row0 + ty*8 + i;
        #pragma unroll
        for (int j = 0; j < 8; j++) {
            int c = col0 + tx*8 + j;
            C[r*N + c] = acc[i][j] + bias[c];
        }
    }
}

// ---------------- LSTM step ----------------
__global__ void lstm_step_kernel(const float* __restrict__ xpart, const float* __restrict__ whhT,
                                 const float* __restrict__ h_in, const float* __restrict__ c_in,
                                 float* __restrict__ h_out, float* __restrict__ c_out,
                                 float* __restrict__ hs, int t) {
    int b = blockIdx.y;
    int j = blockIdx.x*blockDim.x + threadIdx.x;
    __shared__ float sh[HID];
    for (int k = threadIdx.x; k < HID; k += blockDim.x) sh[k] = h_in[b*HID + k];
    __syncthreads();
    const float* xp = xpart + (long)(b*TS + t)*4*HID;
    float gi = xp[j], gf = xp[HID + j], gg = xp[2*HID + j], go = xp[3*HID + j];
    for (int k = 0; k < HID; k++) {
        float hv = sh[k];
        const float* wr = whhT + (long)k*4*HID;
        gi += hv * wr[j];
        gf += hv * wr[HID + j];
        gg += hv * wr[2*HID + j];
        go += hv * wr[3*HID + j];
    }
    float si = 1.f/(1.f + expf(-gi));
    float sf = 1.f/(1.f + expf(-gf));
    float tg = tanhf(gg);
    float so = 1.f/(1.f + expf(-go));
    float cn = sf * c_in[b*HID + j] + si * tg;
    float hn = so * tanhf(cn);
    c_out[b*HID + j] = cn;
    h_out[b*HID + j] = hn;
    hs[(long)(b*TS + t)*HID + j] = hn;
}

// ---------------- host launch ----------------
extern "C" void kernel_launch(void* const* d_in, const int* in_sizes, int n_in,
                              void* d_out, int out_size) {
    const float* images   = (const float*)d_in[0];
    const int*   captions = (const int*)  d_in[1];
    const float* w1  = (const float*)d_in[2];
    const float* g1  = (const float*)d_in[3];
    const float* be1 = (const float*)d_in[4];
    const float* w2  = (const float*)d_in[5];
    const float* g2  = (const float*)d_in[6];
    const float* be2 = (const float*)d_in[7];
    const float* w3  = (const float*)d_in[8];
    const float* g3  = (const float*)d_in[9];
    const float* be3 = (const float*)d_in[10];
    const float* w4  = (const float*)d_in[11];
    const float* g4  = (const float*)d_in[12];
    const float* be4 = (const float*)d_in[13];
    const float* pw  = (const float*)d_in[14];
    const float* pb  = (const float*)d_in[15];
    const float* emb = (const float*)d_in[16];
    const float* ihw = (const float*)d_in[17];
    const float* ihb = (const float*)d_in[18];
    const float* icw = (const float*)d_in[19];
    const float* icb = (const float*)d_in[20];
    const float* wih = (const float*)d_in[21];
    const float* whh = (const float*)d_in[22];
    const float* bih = (const float*)d_in[23];
    const float* bhh = (const float*)d_in[24];
    const float* ow  = (const float*)d_in[25];
    const float* ob  = (const float*)d_in[26];
    float* out = (float*)d_out;

    float *col, *act1, *pool1, *act2, *act3, *act4, *w1p, *part1, *part2, *bna, *bnb;
    float *feats, *enc, *xs, *xpart, *wihT, *whhT, *hs, *h0, *h1, *c0, *c1;
    cudaGetSymbolAddress((void**)&col,   g_col);
    cudaGetSymbolAddress((void**)&act1,  g_act1);
    cudaGetSymbolAddress((void**)&pool1, g_pool1);
    cudaGetSymbolAddress((void**)&act2,  g_act2);
    cudaGetSymbolAddress((void**)&act3,  g_act3);
    cudaGetSymbolAddress((void**)&act4,  g_act4);
    cudaGetSymbolAddress((void**)&w1p,   g_w1p);
    cudaGetSymbolAddress((void**)&part1, g_part1);
    cudaGetSymbolAddress((void**)&part2, g_part2);
    cudaGetSymbolAddress((void**)&bna,   g_bna);
    cudaGetSymbolAddress((void**)&bnb,   g_bnb);
    cudaGetSymbolAddress((void**)&feats, g_feats);
    cudaGetSymbolAddress((void**)&enc,   g_enc);
    cudaGetSymbolAddress((void**)&xs,    g_xs);
    cudaGetSymbolAddress((void**)&xpart, g_xpart);
    cudaGetSymbolAddress((void**)&wihT,  g_wihT);
    cudaGetSymbolAddress((void**)&whhT,  g_whhT);
    cudaGetSymbolAddress((void**)&hs,    g_hs);
    cudaGetSymbolAddress((void**)&h0,    g_h);
    cudaGetSymbolAddress((void**)&c0,    g_c);
    h1 = h0 + BB*HID;
    c1 = c0 + BB*HID;

    // ===== conv1: im2col(7x7) + GEMM =====
    padw1_kernel<<<40, 256>>>(w1, w1p);
    im2col7_kernel<<<(160*401408 + 255)/256, 256>>>(images, col);
    convgemm_kernel<<<dim3(401408/64, 1), 256>>>(w1p, col, act1, 64, 401408, 160, 401408, 12544, 64);
    bn_stats_part_kernel<<<dim3(64, 32), 256>>>(act1, part1, part2, 32, 64, 12544, 32);
    bn_finalize_kernel<<<1, 256>>>(part1, part2, g1, be1, bna, bnb, 64, 32, 1.f/(32.f*12544.f));
    maxpool_bn_kernel<<<(32*64*56*56 + 255)/256, 256>>>(act1, pool1, bna, bnb);

    // ===== conv2: im2col(3x3, plain) + GEMM =====
    im2col3_kernel<<<(576*25088 + 255)/256, 256>>>(pool1, col, nullptr, nullptr,
                                                   64, 56, 28, 784, 25088, 25088, 576*25088);
    convgemm_kernel<<<dim3(25088/64, 2), 256>>>(w2, col, act2, 128, 25088, 576, 25088, 784, 128);
    bn_stats_part_kernel<<<dim3(128, 32), 256>>>(act2, part1, part2, 32, 128, 784, 32);
    bn_finalize_kernel<<<1, 256>>>(part1, part2, g2, be2, bna, bnb, 128, 32, 1.f/(32.f*784.f));

    // ===== conv3: im2col(3x3, fused bn2+relu) + GEMM =====
    im2col3_kernel<<<(1152*6272 + 255)/256, 256>>>(act2, col, bna, bnb,
                                                   128, 28, 14, 196, 6272, 6272, 1152*6272);
    convgemm_kernel<<<dim3(6272/64, 4), 256>>>(w3, col, act3, 256, 6272, 1152, 6272, 196, 256);
    bn_stats_part_kernel<<<dim3(256, 16), 256>>>(act3, part1, part2, 32, 256, 196, 16);
    bn_finalize_kernel<<<1, 256>>>(part1, part2, g3, be3, bna, bnb, 256, 16, 1.f/(32.f*196.f));

    // ===== conv4: im2col(3x3, fused bn3+relu, N padded 1568->1600) + GEMM =====
    im2col3_kernel<<<(2304*1600 + 255)/256, 256>>>(act3, col, bna, bnb,
                                                   256, 14, 7, 49, 1600, 1568, 2304*1600);
    convgemm_kernel<<<dim3(1600/64, 8), 256>>>(w4, col, act4, 512, 1600, 2304, 1568, 49, 512);
    bn_stats_part_kernel<<<dim3(512, 8), 256>>>(act4, part1, part2, 32, 512, 49, 8);
    bn_finalize_kernel<<<2, 256>>>(part1, part2, g4, be4, bna, bnb, 512, 8, 1.f/(32.f*49.f));

    // ===== fused bn4+relu+avgpool =====
    avgpool_bn_kernel<<<64, 256>>>(act4, feats, bna, bnb);

    // ===== encoder -> LSTM init =====
    fc_kernel<<<64, 256>>>(feats, pw, pb, enc, BB, EMB, 512, 0);
    fc_kernel<<<64, 256>>>(enc, ihw, ihb, h0, BB, HID, EMB, 1);
    fc_kernel<<<64, 256>>>(enc, icw, icb, c0, BB, HID, EMB, 1);

    // ===== weight transposes =====
    transpose_kernel<<<dim3(512/32, 2048/32), dim3(32, 32)>>>(wih, wihT, 4*HID, EMB);
    transpose_kernel<<<dim3(512/32, 2048/32), dim3(32, 32)>>>(whh, whhT, 4*HID, HID);

    // ===== embedding + input projection (biases folded) =====
    embed_kernel<<<(BB*TS*EMB + 255)/256, 256>>>(captions, emb, xs);
    sgemm_bias_kernel<<<dim3(2048/64, 640/64), 256>>>(xs, wihT, bih, bhh, xpart, 640, 2048, 512);

    // ===== LSTM scan =====
    float* hbuf[2] = { h0, h1 };
    float* cbuf[2] = { c0, c1 };
    for (int t = 0; t < TS; t++) {
        lstm_step_kernel<<<dim3(4, 32), 128>>>(xpart, whhT,
                                               hbuf[t & 1], cbuf[t & 1],
                                               hbuf[(t+1) & 1], cbuf[(t+1) & 1],
                                               hs, t);
    }

    // ===== output projection (128x128 tiles) =====
    sgemm128_kernel<<<dim3(32000/128, 640/128), 256>>>(hs, ow, ob, out, 640, 32000, 512);
}

// round 6
// speedup vs baseline: 2.9675x; 1.0143x over previous
#include <cuda_runtime.h>
#include <cuda_bf16.h>
#include <math.h>

// ---------------- problem constants ----------------
#define BB 32
#define EMB 512
#define HID 512
#define VV 32000
#define TT 21
#define TS 20            // T-1 LSTM steps

// ---------------- device scratch ----------------
__device__ float g_col[160*401408];        // im2col buffer (max: conv1)
__device__ float g_act1[32*64*112*112];
__device__ float g_pool1[32*64*56*56];
__device__ float g_act2[32*128*28*28];
__device__ float g_act3[32*256*14*14];
__device__ float g_act4[32*512*7*7];
__device__ float g_w1p[64*160];
__device__ float g_part1[512*32];
__device__ float g_part2[512*32];
__device__ float g_bna[512];
__device__ float g_bnb[512];
__device__ float g_feats[BB*512];
__device__ float g_enc[BB*EMB];
__device__ float g_h[2][BB*HID];
__device__ float g_c[2][BB*HID];
__device__ float g_xs[BB*TS*EMB];
__device__ float g_xpart[BB*TS*4*HID];
__device__ float g_wihT[EMB*4*HID];
__device__ float g_whhT[HID*4*HID];
__device__ float g_hs[BB*TS*HID];

// ---------------- pad conv1 weights [64,147] -> [64,160] ----------------
__global__ void padw1_kernel(const float* __restrict__ w, float* __restrict__ wp) {
    int idx = blockIdx.x*blockDim.x + threadIdx.x;
    if (idx >= 64*160) return;
    int co = idx / 160, k = idx % 160;
    wp[idx] = (k < 147) ? w[co*147 + k] : 0.f;
}

// ---------------- im2col for conv1: 7x7 s2 p3, 3ch, 224->112, K padded to 160 ----------------
__global__ void im2col7_kernel(const float* __restrict__ in, float* __restrict__ Bm) {
    int idx = blockIdx.x*blockDim.x + threadIdx.x;
    const int Npad = 401408;          // 32*112*112
    if (idx >= 160*Npad) return;
    int k = idx / Npad, col = idx - k*Npad;
    float v = 0.f;
    if (k < 147) {
        int ci = k / 49, r = k - ci*49;
        int kh = r / 7, kw = r - kh*7;
        int n = col / 12544, hw = col - n*12544;
        int oh = hw / 112, ow = hw - oh*112;
        int ih = oh*2 - 3 + kh, iw = ow*2 - 3 + kw;
        if ((unsigned)ih < 224u && (unsigned)iw < 224u)
            v = in[((long)(n*3 + ci)*224 + ih)*224 + iw];
    }
    Bm[idx] = v;
}

// ---------------- im2col for 3x3 s2 p1 conv, optional fused BN+ReLU on input ----------------
__global__ void im2col3_kernel(const float* __restrict__ in, float* __restrict__ Bm,
                               const float* __restrict__ a, const float* __restrict__ bsh,
                               int Cin, int Hin, int Wout, int HW, int Npad, int Ntrue, int total) {
    int idx = blockIdx.x*blockDim.x + threadIdx.x;
    if (idx >= total) return;
    int k = idx / Npad, col = idx - k*Npad;
    float v = 0.f;
    if (col < Ntrue) {
        int ci = k / 9, r = k - ci*9;
        int kh = r / 3, kw = r - kh*3;
        int n = col / HW, hw = col - n*HW;
        int oh = hw / Wout, ow = hw - oh*Wout;
        int ih = oh*2 - 1 + kh, iw = ow*2 - 1 + kw;
        if ((unsigned)ih < (unsigned)Hin && (unsigned)iw < (unsigned)Hin) {
            float x = in[((long)(n*Cin + ci)*Hin + ih)*Hin + iw];
            if (a) { x = a[ci]*x + bsh[ci]; x = x > 0.f ? x : 0.f; }
            v = x;
        }
    }
    Bm[idx] = v;
}

// ---------------- conv GEMM 64x128x16: for conv1 (M=64) ----------------
__global__ void convgemm64_kernel(const float* __restrict__ A, const float* __restrict__ B,
                                  float* __restrict__ out, int Npad, int K,
                                  int Ntrue, int HW, int Cout) {
    __shared__ float As[16][64];
    __shared__ float Bs[16][128];
    int tid = threadIdx.x;
    int ty = tid >> 4, tx = tid & 15;          // 16x16; thread tile 4(m) x 8(n)
    int col0 = blockIdx.x*128;
    float acc[4][8] = {};
    int ar_ = tid >> 2;                        // 0..63
    int ak4 = (tid & 3) * 4;
    int bk_ = tid >> 5;                        // 0..7
    int bn4 = (tid & 31) * 4;
    for (int k0 = 0; k0 < K; k0 += 16) {
        float4 av = *(const float4*)(A + (long)ar_*K + k0 + ak4);
        As[ak4  ][ar_] = av.x; As[ak4+1][ar_] = av.y;
        As[ak4+2][ar_] = av.z; As[ak4+3][ar_] = av.w;
        float4 b0 = *(const float4*)(B + (long)(k0 + bk_    )*Npad + col0 + bn4);
        float4 b1 = *(const float4*)(B + (long)(k0 + bk_ + 8)*Npad + col0 + bn4);
        *(float4*)&Bs[bk_    ][bn4] = b0;
        *(float4*)&Bs[bk_ + 8][bn4] = b1;
        __syncthreads();
        #pragma unroll
        for (int k = 0; k < 16; k++) {
            float ar[4], br[8];
            #pragma unroll
            for (int i = 0; i < 4; i++) ar[i] = As[k][ty*4 + i];
            *(float4*)(br)   = *(const float4*)&Bs[k][tx*8];
            *(float4*)(br+4) = *(const float4*)&Bs[k][tx*8 + 4];
            #pragma unroll
            for (int i = 0; i < 4; i++)
                #pragma unroll
                for (int j = 0; j < 8; j++) acc[i][j] += ar[i]*br[j];
        }
        __syncthreads();
    }
    #pragma unroll
    for (int i = 0; i < 4; i++) {
        int co = ty*4 + i;
        #pragma unroll
        for (int j = 0; j < 8; j++) {
            int col = col0 + tx*8 + j;
            if (col < Ntrue) {
                int n = col / HW, hw = col - n*HW;
                out[((long)(n*Cout + co))*HW + hw] = acc[i][j];
            }
        }
    }
}

// ---------------- conv GEMM 128x128x16 scatter (conv2/3/4) ----------------
__global__ void convgemm128_kernel(const float* __restrict__ A, const float* __restrict__ B,
                                   float* __restrict__ out, int Npad, int K,
                                   int Ntrue, int HW, int Cout) {
    __shared__ float As[16][128];
    __shared__ float Bs[16][128];
    int tid = threadIdx.x;
    int ty = tid >> 4, tx = tid & 15;
    int row0 = blockIdx.y*128, col0 = blockIdx.x*128;
    float acc[8][8] = {};
    int ar_ = tid >> 2;
    int ak4 = (tid & 3) * 4;
    int bk_ = tid >> 5;
    int bn4 = (tid & 31) * 4;
    for (int k0 = 0; k0 < K; k0 += 16) {
        float4 a0 = *(const float4*)(A + (long)(row0 + ar_     )*K + k0 + ak4);
        float4 a1 = *(const float4*)(A + (long)(row0 + ar_ + 64)*K + k0 + ak4);
        As[ak4  ][ar_] = a0.x; As[ak4+1][ar_] = a0.y;
        As[ak4+2][ar_] = a0.z; As[ak4+3][ar_] = a0.w;
        As[ak4  ][ar_+64] = a1.x; As[ak4+1][ar_+64] = a1.y;
        As[ak4+2][ar_+64] = a1.z; As[ak4+3][ar_+64] = a1.w;
        float4 b0 = *(const float4*)(B + (long)(k0 + bk_    )*Npad + col0 + bn4);
        float4 b1 = *(const float4*)(B + (long)(k0 + bk_ + 8)*Npad + col0 + bn4);
        *(float4*)&Bs[bk_    ][bn4] = b0;
        *(float4*)&Bs[bk_ + 8][bn4] = b1;
        __syncthreads();
        #pragma unroll
        for (int k = 0; k < 16; k++) {
            float ar[8], br[8];
            *(float4*)(ar)   = *(const float4*)&As[k][ty*8];
            *(float4*)(ar+4) = *(const float4*)&As[k][ty*8 + 4];
            *(float4*)(br)   = *(const float4*)&Bs[k][tx*8];
            *(float4*)(br+4) = *(const float4*)&Bs[k][tx*8 + 4];
            #pragma unroll
            for (int i = 0; i < 8; i++)
                #pragma unroll
                for (int j = 0; j < 8; j++) acc[i][j] += ar[i]*br[j];
        }
        __syncthreads();
    }
    #pragma unroll
    for (int i = 0; i < 8; i++) {
        int co = row0 + ty*8 + i;
        #pragma unroll
        for (int j = 0; j < 8; j++) {
            int col = col0 + tx*8 + j;
            if (col < Ntrue) {
                int n = col / HW, hw = col - n*HW;
                out[((long)(n*Cout + co))*HW + hw] = acc[i][j];
            }
        }
    }
}

// ---------------- BN partial stats (deterministic) ----------------
__global__ void bn_stats_part_kernel(const float* __restrict__ x, float* __restrict__ part1,
                                     float* __restrict__ part2, int N, int C, int HW, int S) {
    int c = blockIdx.x, s0 = blockIdx.y;
    float s = 0.f, s2 = 0.f;
    for (int n = s0; n < N; n += S) {
        const float* p = x + ((long)n*C + c)*HW;
        for (int i = threadIdx.x; i < HW; i += blockDim.x) {
            float v = p[i];
            s += v; s2 += v*v;
        }
    }
    __shared__ float ss[256], ss2[256];
    ss[threadIdx.x] = s; ss2[threadIdx.x] = s2;
    __syncthreads();
    for (int o = 128; o > 0; o >>= 1) {
        if (threadIdx.x < o) { ss[threadIdx.x] += ss[threadIdx.x+o]; ss2[threadIdx.x] += ss2[threadIdx.x+o]; }
        __syncthreads();
    }
    if (threadIdx.x == 0) {
        part1[c*S + s0] = ss[0];
        part2[c*S + s0] = ss2[0];
    }
}

__global__ void bn_finalize_kernel(const float* __restrict__ part1, const float* __restrict__ part2,
                                   const float* __restrict__ g, const float* __restrict__ be,
                                   float* __restrict__ a, float* __restrict__ bsh,
                                   int C, int S, float invcnt) {
    int c = blockIdx.x*blockDim.x + threadIdx.x;
    if (c >= C) return;
    float s = 0.f, s2 = 0.f;
    for (int i = 0; i < S; i++) { s += part1[c*S + i]; s2 += part2[c*S + i]; }
    float m = s*invcnt;
    float var = s2*invcnt - m*m;
    float r = rsqrtf(var + 1e-5f);
    float av = g[c]*r;
    a[c] = av;
    bsh[c] = be[c] - m*av;
}

// ---------------- fused BN + maxpool 3x3 s2 p1 + ReLU, 112->56 ----------------
__global__ void maxpool_bn_kernel(const float* __restrict__ x, float* __restrict__ y,
                                  const float* __restrict__ a, const float* __restrict__ bsh) {
    int idx = blockIdx.x*blockDim.x + threadIdx.x;
    const int total = 32*64*56*56;
    if (idx >= total) return;
    int ow = idx % 56, oh = (idx/56) % 56;
    int nc = idx / (56*56);
    int c = nc % 64;
    float ac = a[c], bc = bsh[c];
    const float* p = x + (long)nc*112*112;
    float m = -INFINITY;
    #pragma unroll
    for (int kh = 0; kh < 3; kh++) {
        int ih = oh*2 - 1 + kh;
        if ((unsigned)ih >= 112u) continue;
        #pragma unroll
        for (int kw = 0; kw < 3; kw++) {
            int iw = ow*2 - 1 + kw;
            if ((unsigned)iw >= 112u) continue;
            float v = ac*p[ih*112 + iw] + bc;
            m = v > m ? v : m;
        }
    }
    y[idx] = m > 0.f ? m : 0.f;
}

// ---------------- fused BN + ReLU + global avg pool 7x7 ----------------
__global__ void avgpool_bn_kernel(const float* __restrict__ x, float* __restrict__ y,
                                  const float* __restrict__ a, const float* __restrict__ bsh) {
    int idx = blockIdx.x*blockDim.x + threadIdx.x;
    if (idx >= BB*512) return;
    int c = idx % 512;
    float ac = a[c], bc = bsh[c];
    const float* p = x + (long)idx*49;
    float s = 0.f;
    #pragma unroll
    for (int i = 0; i < 49; i++) {
        float v = ac*p[i] + bc;
        s += v > 0.f ? v : 0.f;
    }
    y[idx] = s * (1.f/49.f);
}

// ---------------- small FC: out[M,N] = A[M,K] @ B[K,N] + bias (opt tanh) ----------------
__global__ void fc_kernel(const float* __restrict__ A, const float* __restrict__ Bm,
                          const float* __restrict__ bias, float* __restrict__ out,
                          int M, int N, int K, int act) {
    int idx = blockIdx.x*blockDim.x + threadIdx.x;
    if (idx >= M*N) return;
    int m = idx / N, n = idx % N;
    float acc = bias ? bias[n] : 0.f;
    const float* a = A + (long)m*K;
    for (int k = 0; k < K; k++) acc += a[k] * Bm[(long)k*N + n];
    if (act) acc = tanhf(acc);
    out[idx] = acc;
}

// ---------------- transpose [R,C] -> [C,R] ----------------
__global__ void transpose_kernel(const float* __restrict__ a, float* __restrict__ at,
                                 int R, int C) {
    __shared__ float tile[32][33];
    int r = blockIdx.y*32 + threadIdx.y;
    int c = blockIdx.x*32 + threadIdx.x;
    if (r < R && c < C) tile[threadIdx.y][threadIdx.x] = a[(long)r*C + c];
    __syncthreads();
    int r2 = blockIdx.x*32 + threadIdx.y;
    int c2 = blockIdx.y*32 + threadIdx.x;
    if (r2 < C && c2 < R) at[(long)r2*R + c2] = tile[threadIdx.x][threadIdx.y];
}

// ---------------- embedding gather ----------------
__global__ void embed_kernel(const int* __restrict__ captions, const float* __restrict__ emb,
                             float* __restrict__ xs) {
    int idx = blockIdx.x*blockDim.x + threadIdx.x;
    if (idx >= BB*TS*EMB) return;
    int e = idx % EMB;
    int r = idx / EMB;
    int b = r / TS, t = r % TS;
    int tok = captions[b*TT + t];
    xs[idx] = emb[(long)tok*EMB + e];
}

// ---------------- 128x128x16 SGEMM + dual bias (xpart) ----------------
__global__ void sgemm128_kernel(const float* __restrict__ A, const float* __restrict__ B,
                                const float* __restrict__ bias1, const float* __restrict__ bias2,
                                float* __restrict__ C, int M, int N, int K) {
    __shared__ float As[16][128];
    __shared__ float Bs[16][128];
    int tid = threadIdx.x;
    int ty = tid >> 4, tx = tid & 15;
    int row0 = blockIdx.y*128, col0 = blockIdx.x*128;
    float acc[8][8] = {};
    int ar_ = tid >> 2;
    int ak4 = (tid & 3) * 4;
    int bk_ = tid >> 5;
    int bn4 = (tid & 31) * 4;
    for (int k0 = 0; k0 < K; k0 += 16) {
        float4 a0 = *(const float4*)(A + (long)(row0 + ar_     )*K + k0 + ak4);
        float4 a1 = *(const float4*)(A + (long)(row0 + ar_ + 64)*K + k0 + ak4);
        As[ak4  ][ar_] = a0.x; As[ak4+1][ar_] = a0.y;
        As[ak4+2][ar_] = a0.z; As[ak4+3][ar_] = a0.w;
        As[ak4  ][ar_+64] = a1.x; As[ak4+1][ar_+64] = a1.y;
        As[ak4+2][ar_+64] = a1.z; As[ak4+3][ar_+64] = a1.w;
        float4 b0 = *(const float4*)(B + (long)(k0 + bk_    )*N + col0 + bn4);
        float4 b1 = *(const float4*)(B + (long)(k0 + bk_ + 8)*N + col0 + bn4);
        *(float4*)&Bs[bk_    ][bn4] = b0;
        *(float4*)&Bs[bk_ + 8][bn4] = b1;
        __syncthreads();
        #pragma unroll
        for (int k = 0; k < 16; k++) {
            float ar[8], br[8];
            *(float4*)(ar)   = *(const float4*)&As[k][ty*8];
            *(float4*)(ar+4) = *(const float4*)&As[k][ty*8 + 4];
            *(float4*)(br)   = *(const float4*)&Bs[k][tx*8];
            *(float4*)(br+4) = *(const float4*)&Bs[k][tx*8 + 4];
            #pragma unroll
            for (int i = 0; i < 8; i++)
                #pragma unroll
                for (int j = 0; j < 8; j++) acc[i][j] += ar[i]*br[j];
        }
        __syncthreads();
    }
    #pragma unroll
    for (int i = 0; i < 8; i++) {
        long r = row0 + ty*8 + i;
        #pragma unroll
        for (int j = 0; j < 8; j++) {
            int c = col0 + tx*8 + j;
            float v = acc[i][j];
            if (bias1) v += bias1[c];
            if (bias2) v += bias2[c];
            C[r*N + c] = v;
        }
    }
}

// ---------------- tf32 tensor-core GEMM + bias (logits) ----------------
// C[M,N] = A[M,K]@B[K,N] + bias.  BM=BN=128, BK=32, 256 thr (8 warps = 2m x 4n),
// warp tile 64x32 via mma.sync.m16n8k8 (4 m-tiles x 4 n-tiles).
__global__ void tf32gemm_kernel(const float* __restrict__ A, const float* __restrict__ B,
                                const float* __restrict__ bias, float* __restrict__ C,
                                int M, int N, int K) {
    __shared__ unsigned As[32][132];
    __shared__ unsigned Bs[32][132];
    int tid = threadIdx.x;
    int warp = tid >> 5, lane = tid & 31;
    int wm = warp >> 2, wn = warp & 3;
    int row0 = blockIdx.y*128, col0 = blockIdx.x*128;
    int ar = tid >> 3, akq = (tid & 7) * 4;        // A: rows ar+32i, k quad akq
    int bkr = tid >> 5, bnq = (tid & 31) * 4;      // B: rows bkr+8j, n quad bnq
    int lq = lane & 3, lr = lane >> 2;             // lane quad pos / group
    float c[4][4][4];
    #pragma unroll
    for (int i = 0; i < 4; i++)
        #pragma unroll
        for (int j = 0; j < 4; j++)
            #pragma unroll
            for (int q = 0; q < 4; q++) c[i][j][q] = 0.f;

    for (int k0 = 0; k0 < K; k0 += 32) {
        #pragma unroll
        for (int i = 0; i < 4; i++) {
            float4 av = *(const float4*)(A + (long)(row0 + ar + 32*i)*K + k0 + akq);
            unsigned t0, t1, t2, t3;
            asm("cvt.rna.tf32.f32 %0, %1;" : "=r"(t0) : "f"(av.x));
            asm("cvt.rna.tf32.f32 %0, %1;" : "=r"(t1) : "f"(av.y));
            asm("cvt.rna.tf32.f32 %0, %1;" : "=r"(t2) : "f"(av.z));
            asm("cvt.rna.tf32.f32 %0, %1;" : "=r"(t3) : "f"(av.w));
            As[akq  ][ar + 32*i] = t0; As[akq+1][ar + 32*i] = t1;
            As[akq+2][ar + 32*i] = t2; As[akq+3][ar + 32*i] = t3;
        }
        #pragma unroll
        for (int j = 0; j < 4; j++) {
            float4 bv = *(const float4*)(B + (long)(k0 + bkr + 8*j)*N + col0 + bnq);
            unsigned t0, t1, t2, t3;
            asm("cvt.rna.tf32.f32 %0, %1;" : "=r"(t0) : "f"(bv.x));
            asm("cvt.rna.tf32.f32 %0, %1;" : "=r"(t1) : "f"(bv.y));
            asm("cvt.rna.tf32.f32 %0, %1;" : "=r"(t2) : "f"(bv.z));
            asm("cvt.rna.tf32.f32 %0, %1;" : "=r"(t3) : "f"(bv.w));
            Bs[bkr + 8*j][bnq  ] = t0; Bs[bkr + 8*j][bnq+1] = t1;
            Bs[bkr + 8*j][bnq+2] = t2; Bs[bkr + 8*j][bnq+3] = t3;
        }
        __syncthreads();
        #pragma unroll
        for (int k8 = 0; k8 < 32; k8 += 8) {
            unsigned a[4][4], b[4][2];
            #pragma unroll
            for (int mi = 0; mi < 4; mi++) {
                int m0 = wm*64 + mi*16;
                a[mi][0] = As[k8 + lq    ][m0 + lr    ];
                a[mi][1] = As[k8 + lq    ][m0 + lr + 8];
                a[mi][2] = As[k8 + lq + 4][m0 + lr    ];
                a[mi][3] = As[k8 + lq + 4][m0 + lr + 8];
            }
            #pragma unroll
            for (int ni = 0; ni < 4; ni++) {
                int n0 = wn*32 + ni*8;
                b[ni][0] = Bs[k8 + lq    ][n0 + lr];
                b[ni][1] = Bs[k8 + lq + 4][n0 + lr];
            }
            #pragma unroll
            for (int mi = 0; mi < 4; mi++)
                #pragma unroll
                for (int ni = 0; ni < 4; ni++) {
                    asm volatile(
                        "mma.sync.aligned.m16n8k8.row.col.f32.tf32.tf32.f32 "
                        "{%0,%1,%2,%3}, {%4,%5,%6,%7}, {%8,%9}, {%0,%1,%2,%3};"
                        : "+f"(c[mi][ni][0]), "+f"(c[mi][ni][1]),
                          "+f"(c[mi][ni][2]), "+f"(c[mi][ni][3])
                        : "r"(a[mi][0]), "r"(a[mi][1]), "r"(a[mi][2]), "r"(a[mi][3]),
                          "r"(b[ni][0]), "r"(b[ni][1]));
                }
        }
        __syncthreads();
    }
    #pragma unroll
    for (int mi = 0; mi < 4; mi++) {
        int rbase = row0 + wm*64 + mi*16 + lr;
        #pragma unroll
        for (int ni = 0; ni < 4; ni++) {
            int cbase = col0 + wn*32 + ni*8 + lq*2;
            float b0 = bias[cbase], b1 = bias[cbase + 1];
            C[(long)rbase*N + cbase]           = c[mi][ni][0] + b0;
            C[(long)rbase*N + cbase + 1]       = c[mi][ni][1] + b1;
            C[(long)(rbase + 8)*N + cbase]     = c[mi][ni][2] + b0;
            C[(long)(rbase + 8)*N + cbase + 1] = c[mi][ni][3] + b1;
        }
    }
}

// ---------------- LSTM step ----------------
__global__ void lstm_step_kernel(const float* __restrict__ xpart, const float* __restrict__ whhT,
                                 const float* __restrict__ h_in, const float* __restrict__ c_in,
                                 float* __restrict__ h_out, float* __restrict__ c_out,
                                 float* __restrict__ hs, int t) {
    int b = blockIdx.y;
    int j = blockIdx.x*blockDim.x + threadIdx.x;
    __shared__ float sh[HID];
    for (int k = threadIdx.x; k < HID; k += blockDim.x) sh[k] = h_in[b*HID + k];
    __syncthreads();
    const float* xp = xpart + (long)(b*TS + t)*4*HID;
    float gi = xp[j], gf = xp[HID + j], gg = xp[2*HID + j], go = xp[3*HID + j];
    for (int k = 0; k < HID; k++) {
        float hv = sh[k];
        const float* wr = whhT + (long)k*4*HID;
        gi += hv * wr[j];
        gf += hv * wr[HID + j];
        gg += hv * wr[2*HID + j];
        go += hv * wr[3*HID + j];
    }
    float si = 1.f/(1.f + expf(-gi));
    float sf = 1.f/(1.f + expf(-gf));
    float tg = tanhf(gg);
    float so = 1.f/(1.f + expf(-go));
    float cn = sf * c_in[b*HID + j] + si * tg;
    float hn = so * tanhf(cn);
    c_out[b*HID + j] = cn;
    h_out[b*HID + j] = hn;
    hs[(long)(b*TS + t)*HID + j] = hn;
}

// ---------------- host launch ----------------
extern "C" void kernel_launch(void* const* d_in, const int* in_sizes, int n_in,
                              void* d_out, int out_size) {
    const float* images   = (const float*)d_in[0];
    const int*   captions = (const int*)  d_in[1];
    const float* w1  = (const float*)d_in[2];
    const float* g1  = (const float*)d_in[3];
    const float* be1 = (const float*)d_in[4];
    const float* w2  = (const float*)d_in[5];
    const float* g2  = (const float*)d_in[6];
    const float* be2 = (const float*)d_in[7];
    const float* w3  = (const float*)d_in[8];
    const float* g3  = (const float*)d_in[9];
    const float* be3 = (const float*)d_in[10];
    const float* w4  = (const float*)d_in[11];
    const float* g4  = (const float*)d_in[12];
    const float* be4 = (const float*)d_in[13];
    const float* pw  = (const float*)d_in[14];
    const float* pb  = (const float*)d_in[15];
    const float* emb = (const float*)d_in[16];
    const float* ihw = (const float*)d_in[17];
    const float* ihb = (const float*)d_in[18];
    const float* icw = (const float*)d_in[19];
    const float* icb = (const float*)d_in[20];
    const float* wih = (const float*)d_in[21];
    const float* whh = (const float*)d_in[22];
    const float* bih = (const float*)d_in[23];
    const float* bhh = (const float*)d_in[24];
    const float* ow  = (const float*)d_in[25];
    const float* ob  = (const float*)d_in[26];
    float* out = (float*)d_out;

    float *col, *act1, *pool1, *act2, *act3, *act4, *w1p, *part1, *part2, *bna, *bnb;
    float *feats, *enc, *xs, *xpart, *wihT, *whhT, *hs, *h0, *h1, *c0, *c1;
    cudaGetSymbolAddress((void**)&col,   g_col);
    cudaGetSymbolAddress((void**)&act1,  g_act1);
    cudaGetSymbolAddress((void**)&pool1, g_pool1);
    cudaGetSymbolAddress((void**)&act2,  g_act2);
    cudaGetSymbolAddress((void**)&act3,  g_act3);
    cudaGetSymbolAddress((void**)&act4,  g_act4);
    cudaGetSymbolAddress((void**)&w1p,   g_w1p);
    cudaGetSymbolAddress((void**)&part1, g_part1);
    cudaGetSymbolAddress((void**)&part2, g_part2);
    cudaGetSymbolAddress((void**)&bna,   g_bna);
    cudaGetSymbolAddress((void**)&bnb,   g_bnb);
    cudaGetSymbolAddress((void**)&feats, g_feats);
    cudaGetSymbolAddress((void**)&enc,   g_enc);
    cudaGetSymbolAddress((void**)&xs,    g_xs);
    cudaGetSymbolAddress((void**)&xpart, g_xpart);
    cudaGetSymbolAddress((void**)&wihT,  g_wihT);
    cudaGetSymbolAddress((void**)&whhT,  g_whhT);
    cudaGetSymbolAddress((void**)&hs,    g_hs);
    cudaGetSymbolAddress((void**)&h0,    g_h);
    cudaGetSymbolAddress((void**)&c0,    g_c);
    h1 = h0 + BB*HID;
    c1 = c0 + BB*HID;

    // ===== conv1: im2col(7x7) + GEMM (64x128 tiles) =====
    padw1_kernel<<<40, 256>>>(w1, w1p);
    im2col7_kernel<<<(160*401408 + 255)/256, 256>>>(images, col);
    convgemm64_kernel<<<401408/128, 256>>>(w1p, col, act1, 401408, 160, 401408, 12544, 64);
    bn_stats_part_kernel<<<dim3(64, 32), 256>>>(act1, part1, part2, 32, 64, 12544, 32);
    bn_finalize_kernel<<<1, 256>>>(part1, part2, g1, be1, bna, bnb, 64, 32, 1.f/(32.f*12544.f));
    maxpool_bn_kernel<<<(32*64*56*56 + 255)/256, 256>>>(act1, pool1, bna, bnb);

    // ===== conv2: im2col + GEMM (128x128) =====
    im2col3_kernel<<<(576*25088 + 255)/256, 256>>>(pool1, col, nullptr, nullptr,
                                                   64, 56, 28, 784, 25088, 25088, 576*25088);
    convgemm128_kernel<<<dim3(25088/128, 1), 256>>>(w2, col, act2, 25088, 576, 25088, 784, 128);
    bn_stats_part_kernel<<<dim3(128, 32), 256>>>(act2, part1, part2, 32, 128, 784, 32);
    bn_finalize_kernel<<<1, 256>>>(part1, part2, g2, be2, bna, bnb, 128, 32, 1.f/(32.f*784.f));

    // ===== conv3: im2col(fused bn2+relu) + GEMM =====
    im2col3_kernel<<<(1152*6272 + 255)/256, 256>>>(act2, col, bna, bnb,
                                                   128, 28, 14, 196, 6272, 6272, 1152*6272);
    convgemm128_kernel<<<dim3(6272/128, 2), 256>>>(w3, col, act3, 6272, 1152, 6272, 196, 256);
    bn_stats_part_kernel<<<dim3(256, 16), 256>>>(act3, part1, part2, 32, 256, 196, 16);
    bn_finalize_kernel<<<1, 256>>>(part1, part2, g3, be3, bna, bnb, 256, 16, 1.f/(32.f*196.f));

    // ===== conv4: im2col(fused bn3+relu, N pad 1568->1664) + GEMM =====
    im2col3_kernel<<<(2304*1664 + 255)/256, 256>>>(act3, col, bna, bnb,
                                                   256, 14, 7, 49, 1664, 1568, 2304*1664);
    convgemm128_kernel<<<dim3(1664/128, 4), 256>>>(w4, col, act4, 1664, 2304, 1568, 49, 512);
    bn_stats_part_kernel<<<dim3(512, 8), 256>>>(act4, part1, part2, 32, 512, 49, 8);
    bn_finalize_kernel<<<2, 256>>>(part1, part2, g4, be4, bna, bnb, 512, 8, 1.f/(32.f*49.f));

    // ===== fused bn4+relu+avgpool =====
    avgpool_bn_kernel<<<64, 256>>>(act4, feats, bna, bnb);

    // ===== encoder -> LSTM init =====
    fc_kernel<<<64, 256>>>(feats, pw, pb, enc, BB, EMB, 512, 0);
    fc_kernel<<<64, 256>>>(enc, ihw, ihb, h0, BB, HID, EMB, 1);
    fc_kernel<<<64, 256>>>(enc, icw, icb, c0, BB, HID, EMB, 1);

    // ===== weight transposes =====
    transpose_kernel<<<dim3(512/32, 2048/32), dim3(32, 32)>>>(wih, wihT, 4*HID, EMB);
    transpose_kernel<<<dim3(512/32, 2048/32), dim3(32, 32)>>>(whh, whhT, 4*HID, HID);

    // ===== embedding + input projection (biases folded) =====
    embed_kernel<<<(BB*TS*EMB + 255)/256, 256>>>(captions, emb, xs);
    sgemm128_kernel<<<dim3(2048/128, 640/128), 256>>>(xs, wihT, bih, bhh, xpart, 640, 2048, 512);

    // ===== LSTM scan =====
    float* hbuf[2] = { h0, h1 };
    float* cbuf[2] = { c0, c1 };
    for (int t = 0; t < TS; t++) {
        lstm_step_kernel<<<dim3(4, 32), 128>>>(xpart, whhT,
                                               hbuf[t & 1], cbuf[t & 1],
                                               hbuf[(t+1) & 1], cbuf[(t+1) & 1],
                                               hs, t);
    }

    // ===== output projection: tf32 tensor cores =====
    tf32gemm_kernel<<<dim3(32000/128, 640/128), 256>>>(hs, ow, ob, out, 640, 32000, 512);
}

// round 7
// speedup vs baseline: 2.9774x; 1.0033x over previous
#include <cuda_runtime.h>
#include <cuda_bf16.h>
#include <math.h>

// ---------------- problem constants ----------------
#define BB 32
#define EMB 512
#define HID 512
#define VV 32000
#define TT 21
#define TS 20            // T-1 LSTM steps

// ---------------- device scratch ----------------
__device__ float g_act1[32*64*112*112];
__device__ float g_pool1[32*64*56*56];
__device__ float g_act2[32*128*28*28];
__device__ float g_act3[32*256*14*14];
__device__ float g_act4[32*512*7*7];
__device__ float g_w1p[64*160];
__device__ float g_part1[512*32];
__device__ float g_part2[512*32];
__device__ float g_bna[512];
__device__ float g_bnb[512];
__device__ float g_feats[BB*512];
__device__ float g_enc[BB*EMB];
__device__ float g_h[2][BB*HID];
__device__ float g_c[2][BB*HID];
__device__ float g_xs[BB*TS*EMB];
__device__ float g_xpart[BB*TS*4*HID];      // interleaved: col' = hj*4 + gate
__device__ float g_wihI[EMB*4*HID];         // [e][hj*4+g]
__device__ float g_whhI[HID*4*HID];         // [k][hj*4+g]
__device__ float g_bI[4*HID];               // bih+bhh interleaved
__device__ float g_hs[BB*TS*HID];

// ---------------- pad conv1 weights [64,147] -> [64,160] ----------------
__global__ void padw1_kernel(const float* __restrict__ w, float* __restrict__ wp) {
    int idx = blockIdx.x*blockDim.x + threadIdx.x;
    if (idx >= 64*160) return;
    int co = idx / 160, k = idx % 160;
    wp[idx] = (k < 147) ? w[co*147 + k] : 0.f;
}

// ---------------- implicit-GEMM conv1: 7x7 s2 p3, 3->64, 224->112 ----------------
// K=160 (147 real), tile 64x128x16, 256 thr, 4x8/thread. N = 401408 = 3136*128 exact.
__global__ void iconv7_kernel(const float* __restrict__ W, const float* __restrict__ in,
                              float* __restrict__ out) {
    __shared__ float As[16][64];
    __shared__ float Bs[16][128];
    __shared__ int s_nb[128], s_ih0[128], s_iw0[128];
    int tid = threadIdx.x;
    int col0 = blockIdx.x*128;
    if (tid < 128) {
        int col = col0 + tid;
        int n = col / 12544, hw = col - n*12544;
        int oh = hw / 112, ow = hw - oh*112;
        s_nb[tid]  = n*3*224*224;
        s_ih0[tid] = oh*2 - 3;
        s_iw0[tid] = ow*2 - 3;
    }
    __syncthreads();
    int ty = tid >> 4, tx = tid & 15;
    float acc[4][8] = {};
    int ar_ = tid >> 2, ak4 = (tid & 3)*4;
    int bk_ = tid >> 5, bn0 = (tid & 31)*4;
    for (int k0 = 0; k0 < 160; k0 += 16) {
        float4 av = *(const float4*)(W + ar_*160 + k0 + ak4);
        As[ak4  ][ar_] = av.x; As[ak4+1][ar_] = av.y;
        As[ak4+2][ar_] = av.z; As[ak4+3][ar_] = av.w;
        #pragma unroll
        for (int half = 0; half < 2; half++) {
            int k = k0 + bk_ + half*8;
            float vals[4] = {0.f, 0.f, 0.f, 0.f};
            if (k < 147) {
                int ci = k / 49, r = k - ci*49;
                int kh = r / 7, kw = r - kh*7;
                int cio = ci*224*224;
                #pragma unroll
                for (int j = 0; j < 4; j++) {
                    int cc = bn0 + j;
                    int ih = s_ih0[cc] + kh, iw = s_iw0[cc] + kw;
                    if ((unsigned)ih < 224u && (unsigned)iw < 224u)
                        vals[j] = in[s_nb[cc] + cio + ih*224 + iw];
                }
            }
            Bs[bk_ + half*8][bn0  ] = vals[0];
            Bs[bk_ + half*8][bn0+1] = vals[1];
            Bs[bk_ + half*8][bn0+2] = vals[2];
            Bs[bk_ + half*8][bn0+3] = vals[3];
        }
        __syncthreads();
        #pragma unroll
        for (int k = 0; k < 16; k++) {
            float ar[4], br[8];
            #pragma unroll
            for (int i = 0; i < 4; i++) ar[i] = As[k][ty*4 + i];
            *(float4*)(br)   = *(const float4*)&Bs[k][tx*8];
            *(float4*)(br+4) = *(const float4*)&Bs[k][tx*8 + 4];
            #pragma unroll
            for (int i = 0; i < 4; i++)
                #pragma unroll
                for (int j = 0; j < 8; j++) acc[i][j] += ar[i]*br[j];
        }
        __syncthreads();
    }
    #pragma unroll
    for (int i = 0; i < 4; i++) {
        int co = ty*4 + i;
        #pragma unroll
        for (int j = 0; j < 8; j++) {
            int col = col0 + tx*8 + j;
            int n = col / 12544, hw = col - n*12544;
            out[((long)(n*64 + co))*12544 + hw] = acc[i][j];
        }
    }
}

// ---------------- implicit-GEMM 3x3 s2 p1 conv, fused input BN+ReLU ----------------
// tile 128x128x16, 256 thr, 8x8/thread. K = Cin*9 (mult of 16 for Cin=64/128/256).
__global__ void iconv3_kernel(const float* __restrict__ W, const float* __restrict__ in,
                              const float* __restrict__ af, const float* __restrict__ bf,
                              float* __restrict__ out,
                              int Cin, int Hin, int Wout, int HW, int Ntrue, int Cout) {
    __shared__ float As[16][128];
    __shared__ float Bs[16][128];
    __shared__ int s_nb[128], s_ih0[128], s_iw0[128];
    int tid = threadIdx.x;
    int row0 = blockIdx.y*128, col0 = blockIdx.x*128;
    if (tid < 128) {
        int col = col0 + tid;
        if (col < Ntrue) {
            int n = col / HW, hw = col - n*HW;
            int oh = hw / Wout, ow = hw - oh*Wout;
            s_nb[tid]  = n*Cin*Hin*Hin;
            s_ih0[tid] = oh*2 - 1;
            s_iw0[tid] = ow*2 - 1;
        } else {
            s_nb[tid] = 0; s_ih0[tid] = -100000; s_iw0[tid] = -100000;
        }
    }
    __syncthreads();
    int ty = tid >> 4, tx = tid & 15;
    float acc[8][8] = {};
    int ar_ = tid >> 2, ak4 = (tid & 3)*4;
    int bk_ = tid >> 5, bn0 = (tid & 31)*4;
    int K = Cin*9;
    for (int k0 = 0; k0 < K; k0 += 16) {
        float4 a0 = *(const float4*)(W + (long)(row0 + ar_     )*K + k0 + ak4);
        float4 a1 = *(const float4*)(W + (long)(row0 + ar_ + 64)*K + k0 + ak4);
        As[ak4  ][ar_] = a0.x; As[ak4+1][ar_] = a0.y;
        As[ak4+2][ar_] = a0.z; As[ak4+3][ar_] = a0.w;
        As[ak4  ][ar_+64] = a1.x; As[ak4+1][ar_+64] = a1.y;
        As[ak4+2][ar_+64] = a1.z; As[ak4+3][ar_+64] = a1.w;
        #pragma unroll
        for (int half = 0; half < 2; half++) {
            int k = k0 + bk_ + half*8;
            int ci = k / 9, r = k - ci*9;
            int kh = r / 3, kw = r - kh*3;
            int cio = ci*Hin*Hin;
            float sa = 1.f, sb = 0.f;
            if (af) { sa = af[ci]; sb = bf[ci]; }
            #pragma unroll
            for (int j = 0; j < 4; j++) {
                int cc = bn0 + j;
                float v = 0.f;
                int ih = s_ih0[cc] + kh, iw = s_iw0[cc] + kw;
                if ((unsigned)ih < (unsigned)Hin && (unsigned)iw < (unsigned)Hin) {
                    float x = in[s_nb[cc] + cio + ih*Hin + iw];
                    if (af) { x = fmaf(sa, x, sb); x = x > 0.f ? x : 0.f; }
                    v = x;
                }
                Bs[bk_ + half*8][cc] = v;
            }
        }
        __syncthreads();
        #pragma unroll
        for (int k = 0; k < 16; k++) {
            float ar[8], br[8];
            *(float4*)(ar)   = *(const float4*)&As[k][ty*8];
            *(float4*)(ar+4) = *(const float4*)&As[k][ty*8 + 4];
            *(float4*)(br)   = *(const float4*)&Bs[k][tx*8];
            *(float4*)(br+4) = *(const float4*)&Bs[k][tx*8 + 4];
            #pragma unroll
            for (int i = 0; i < 8; i++)
                #pragma unroll
                for (int j = 0; j < 8; j++) acc[i][j] += ar[i]*br[j];
        }
        __syncthreads();
    }
    #pragma unroll
    for (int i = 0; i < 8; i++) {
        int co = row0 + ty*8 + i;
        #pragma unroll
        for (int j = 0; j < 8; j++) {
            int col = col0 + tx*8 + j;
            if (col < Ntrue) {
                int n = col / HW, hw = col - n*HW;
                out[((long)(n*Cout + co))*HW + hw] = acc[i][j];
            }
        }
    }
}

// ---------------- BN partial stats (deterministic) ----------------
__global__ void bn_stats_part_kernel(const float* __restrict__ x, float* __restrict__ part1,
                                     float* __restrict__ part2, int N, int C, int HW, int S) {
    int c = blockIdx.x, s0 = blockIdx.y;
    float s = 0.f, s2 = 0.f;
    for (int n = s0; n < N; n += S) {
        const float* p = x + ((long)n*C + c)*HW;
        for (int i = threadIdx.x; i < HW; i += blockDim.x) {
            float v = p[i];
            s += v; s2 += v*v;
        }
    }
    __shared__ float ss[256], ss2[256];
    ss[threadIdx.x] = s; ss2[threadIdx.x] = s2;
    __syncthreads();
    for (int o = 128; o > 0; o >>= 1) {
        if (threadIdx.x < o) { ss[threadIdx.x] += ss[threadIdx.x+o]; ss2[threadIdx.x] += ss2[threadIdx.x+o]; }
        __syncthreads();
    }
    if (threadIdx.x == 0) {
        part1[c*S + s0] = ss[0];
        part2[c*S + s0] = ss2[0];
    }
}

__global__ void bn_finalize_kernel(const float* __restrict__ part1, const float* __restrict__ part2,
                                   const float* __restrict__ g, const float* __restrict__ be,
                                   float* __restrict__ a, float* __restrict__ bsh,
                                   int C, int S, float invcnt) {
    int c = blockIdx.x*blockDim.x + threadIdx.x;
    if (c >= C) return;
    float s = 0.f, s2 = 0.f;
    for (int i = 0; i < S; i++) { s += part1[c*S + i]; s2 += part2[c*S + i]; }
    float m = s*invcnt;
    float var = s2*invcnt - m*m;
    float r = rsqrtf(var + 1e-5f);
    float av = g[c]*r;
    a[c] = av;
    bsh[c] = be[c] - m*av;
}

// ---------------- fused BN + maxpool 3x3 s2 p1 + ReLU, 112->56 ----------------
__global__ void maxpool_bn_kernel(const float* __restrict__ x, float* __restrict__ y,
                                  const float* __restrict__ a, const float* __restrict__ bsh) {
    int idx = blockIdx.x*blockDim.x + threadIdx.x;
    const int total = 32*64*56*56;
    if (idx >= total) return;
    int ow = idx % 56, oh = (idx/56) % 56;
    int nc = idx / (56*56);
    int c = nc % 64;
    float ac = a[c], bc = bsh[c];
    const float* p = x + (long)nc*112*112;
    float m = -INFINITY;
    #pragma unroll
    for (int kh = 0; kh < 3; kh++) {
        int ih = oh*2 - 1 + kh;
        if ((unsigned)ih >= 112u) continue;
        #pragma unroll
        for (int kw = 0; kw < 3; kw++) {
            int iw = ow*2 - 1 + kw;
            if ((unsigned)iw >= 112u) continue;
            float v = ac*p[ih*112 + iw] + bc;
            m = v > m ? v : m;
        }
    }
    y[idx] = m > 0.f ? m : 0.f;
}

// ---------------- fused BN + ReLU + global avg pool 7x7 ----------------
__global__ void avgpool_bn_kernel(const float* __restrict__ x, float* __restrict__ y,
                                  const float* __restrict__ a, const float* __restrict__ bsh) {
    int idx = blockIdx.x*blockDim.x + threadIdx.x;
    if (idx >= BB*512) return;
    int c = idx % 512;
    float ac = a[c], bc = bsh[c];
    const float* p = x + (long)idx*49;
    float s = 0.f;
    #pragma unroll
    for (int i = 0; i < 49; i++) {
        float v = ac*p[i] + bc;
        s += v > 0.f ? v : 0.f;
    }
    y[idx] = s * (1.f/49.f);
}

// ---------------- small FC ----------------
__global__ void fc_kernel(const float* __restrict__ A, const float* __restrict__ Bm,
                          const float* __restrict__ bias, float* __restrict__ out,
                          int M, int N, int K, int act) {
    int idx = blockIdx.x*blockDim.x + threadIdx.x;
    if (idx >= M*N) return;
    int m = idx / N, n = idx % N;
    float acc = bias ? bias[n] : 0.f;
    const float* a = A + (long)m*K;
    for (int k = 0; k < K; k++) acc += a[k] * Bm[(long)k*N + n];
    if (act) acc = tanhf(acc);
    out[idx] = acc;
}

// ---------------- interleave-transpose: a[2048][K2] -> at[K2][2048], col'=hj*4+g ----------------
__global__ void itrans_kernel(const float* __restrict__ a, float* __restrict__ at, int K2) {
    int idx = blockIdx.x*blockDim.x + threadIdx.x;
    if (idx >= K2*2048) return;
    int col = idx & 2047, k = idx >> 11;
    int hj = col >> 2, g = col & 3;
    at[idx] = a[(long)((g << 9) + hj)*K2 + k];
}

// ---------------- combined interleaved bias ----------------
__global__ void ibias_kernel(const float* __restrict__ bih, const float* __restrict__ bhh,
                             float* __restrict__ bI) {
    int col = blockIdx.x*blockDim.x + threadIdx.x;
    if (col >= 2048) return;
    int hj = col >> 2, g = col & 3;
    bI[col] = bih[(g << 9) + hj] + bhh[(g << 9) + hj];
}

// ---------------- embedding gather ----------------
__global__ void embed_kernel(const int* __restrict__ captions, const float* __restrict__ emb,
                             float* __restrict__ xs) {
    int idx = blockIdx.x*blockDim.x + threadIdx.x;
    if (idx >= BB*TS*EMB) return;
    int e = idx % EMB;
    int r = idx / EMB;
    int b = r / TS, t = r % TS;
    int tok = captions[b*TT + t];
    xs[idx] = emb[(long)tok*EMB + e];
}

// ---------------- 128x128x16 SGEMM + bias (xpart, interleaved) ----------------
__global__ void sgemm128_kernel(const float* __restrict__ A, const float* __restrict__ B,
                                const float* __restrict__ bias1, const float* __restrict__ bias2,
                                float* __restrict__ C, int M, int N, int K) {
    __shared__ float As[16][128];
    __shared__ float Bs[16][128];
    int tid = threadIdx.x;
    int ty = tid >> 4, tx = tid & 15;
    int row0 = blockIdx.y*128, col0 = blockIdx.x*128;
    float acc[8][8] = {};
    int ar_ = tid >> 2;
    int ak4 = (tid & 3) * 4;
    int bk_ = tid >> 5;
    int bn4 = (tid & 31) * 4;
    for (int k0 = 0; k0 < K; k0 += 16) {
        float4 a0 = *(const float4*)(A + (long)(row0 + ar_     )*K + k0 + ak4);
        float4 a1 = *(const float4*)(A + (long)(row0 + ar_ + 64)*K + k0 + ak4);
        As[ak4  ][ar_] = a0.x; As[ak4+1][ar_] = a0.y;
        As[ak4+2][ar_] = a0.z; As[ak4+3][ar_] = a0.w;
        As[ak4  ][ar_+64] = a1.x; As[ak4+1][ar_+64] = a1.y;
        As[ak4+2][ar_+64] = a1.z; As[ak4+3][ar_+64] = a1.w;
        float4 b0 = *(const float4*)(B + (long)(k0 + bk_    )*N + col0 + bn4);
        float4 b1 = *(const float4*)(B + (long)(k0 + bk_ + 8)*N + col0 + bn4);
        *(float4*)&Bs[bk_    ][bn4] = b0;
        *(float4*)&Bs[bk_ + 8][bn4] = b1;
        __syncthreads();
        #pragma unroll
        for (int k = 0; k < 16; k++) {
            float ar[8], br[8];
            *(float4*)(ar)   = *(const float4*)&As[k][ty*8];
            *(float4*)(ar+4) = *(const float4*)&As[k][ty*8 + 4];
            *(float4*)(br)   = *(const float4*)&Bs[k][tx*8];
            *(float4*)(br+4) = *(const float4*)&Bs[k][tx*8 + 4];
            #pragma unroll
            for (int i = 0; i < 8; i++)
                #pragma unroll
                for (int j = 0; j < 8; j++) acc[i][j] += ar[i]*br[j];
        }
        __syncthreads();
    }
    #pragma unroll
    for (int i = 0; i < 8; i++) {
        long r = row0 + ty*8 + i;
        #pragma unroll
        for (int j = 0; j < 8; j++) {
            int c = col0 + tx*8 + j;
            float v = acc[i][j];
            if (bias1) v += bias1[c];
            if (bias2) v += bias2[c];
            C[r*N + c] = v;
        }
    }
}

// ---------------- tf32 tensor-core GEMM + bias (logits) ----------------
__global__ void tf32gemm_kernel(const float* __restrict__ A, const float* __restrict__ B,
                                const float* __restrict__ bias, float* __restrict__ C,
                                int M, int N, int K) {
    __shared__ unsigned As[32][132];
    __shared__ unsigned Bs[32][132];
    int tid = threadIdx.x;
    int warp = tid >> 5, lane = tid & 31;
    int wm = warp >> 2, wn = warp & 3;
    int row0 = blockIdx.y*128, col0 = blockIdx.x*128;
    int ar = tid >> 3, akq = (tid & 7) * 4;
    int bkr = tid >> 5, bnq = (tid & 31) * 4;
    int lq = lane & 3, lr = lane >> 2;
    float c[4][4][4];
    #pragma unroll
    for (int i = 0; i < 4; i++)
        #pragma unroll
        for (int j = 0; j < 4; j++)
            #pragma unroll
            for (int q = 0; q < 4; q++) c[i][j][q] = 0.f;

    for (int k0 = 0; k0 < K; k0 += 32) {
        #pragma unroll
        for (int i = 0; i < 4; i++) {
            float4 av = *(const float4*)(A + (long)(row0 + ar + 32*i)*K + k0 + akq);
            unsigned t0, t1, t2, t3;
            asm("cvt.rna.tf32.f32 %0, %1;" : "=r"(t0) : "f"(av.x));
            asm("cvt.rna.tf32.f32 %0, %1;" : "=r"(t1) : "f"(av.y));
            asm("cvt.rna.tf32.f32 %0, %1;" : "=r"(t2) : "f"(av.z));
            asm("cvt.rna.tf32.f32 %0, %1;" : "=r"(t3) : "f"(av.w));
            As[akq  ][ar + 32*i] = t0; As[akq+1][ar + 32*i] = t1;
            As[akq+2][ar + 32*i] = t2; As[akq+3][ar + 32*i] = t3;
        }
        #pragma unroll
        for (int j = 0; j < 4; j++) {
            float4 bv = *(const float4*)(B + (long)(k0 + bkr + 8*j)*N + col0 + bnq);
            unsigned t0, t1, t2, t3;
            asm("cvt.rna.tf32.f32 %0, %1;" : "=r"(t0) : "f"(bv.x));
            asm("cvt.rna.tf32.f32 %0, %1;" : "=r"(t1) : "f"(bv.y));
            asm("cvt.rna.tf32.f32 %0, %1;" : "=r"(t2) : "f"(bv.z));
            asm("cvt.rna.tf32.f32 %0, %1;" : "=r"(t3) : "f"(bv.w));
            Bs[bkr + 8*j][bnq  ] = t0; Bs[bkr + 8*j][bnq+1] = t1;
            Bs[bkr + 8*j][bnq+2] = t2; Bs[bkr + 8*j][bnq+3] = t3;
        }
        __syncthreads();
        #pragma unroll
        for (int k8 = 0; k8 < 32; k8 += 8) {
            unsigned a[4][4], b[4][2];
            #pragma unroll
            for (int mi = 0; mi < 4; mi++) {
                int m0 = wm*64 + mi*16;
                a[mi][0] = As[k8 + lq    ][m0 + lr    ];
                a[mi][1] = As[k8 + lq    ][m0 + lr + 8];
                a[mi][2] = As[k8 + lq + 4][m0 + lr    ];
                a[mi][3] = As[k8 + lq + 4][m0 + lr + 8];
            }
            #pragma unroll
            for (int ni = 0; ni < 4; ni++) {
                int n0 = wn*32 + ni*8;
                b[ni][0] = Bs[k8 + lq    ][n0 + lr];
                b[ni][1] = Bs[k8 + lq + 4][n0 + lr];
            }
            #pragma unroll
            for (int mi = 0; mi < 4; mi++)
                #pragma unroll
                for (int ni = 0; ni < 4; ni++) {
                    asm volatile(
                        "mma.sync.aligned.m16n8k8.row.col.f32.tf32.tf32.f32 "
                        "{%0,%1,%2,%3}, {%4,%5,%6,%7}, {%8,%9}, {%0,%1,%2,%3};"
                        : "+f"(c[mi][ni][0]), "+f"(c[mi][ni][1]),
                          "+f"(c[mi][ni][2]), "+f"(c[mi][ni][3])
                        : "r"(a[mi][0]), "r"(a[mi][1]), "r"(a[mi][2]), "r"(a[mi][3]),
                          "r"(b[ni][0]), "r"(b[ni][1]));
                }
        }
        __syncthreads();
    }
    #pragma unroll
    for (int mi = 0; mi < 4; mi++) {
        int rbase = row0 + wm*64 + mi*16 + lr;
        #pragma unroll
        for (int ni = 0; ni < 4; ni++) {
            int cbase = col0 + wn*32 + ni*8 + lq*2;
            float b0 = bias[cbase], b1 = bias[cbase + 1];
            C[(long)rbase*N + cbase]           = c[mi][ni][0] + b0;
            C[(long)rbase*N + cbase + 1]       = c[mi][ni][1] + b1;
            C[(long)(rbase + 8)*N + cbase]     = c[mi][ni][2] + b0;
            C[(long)(rbase + 8)*N + cbase + 1] = c[mi][ni][3] + b1;
        }
    }
}

// ---------------- LSTM step: gates[32,2048] = h[32,512] @ whhI + xpartI; cell update ----------
// Interleaved col' = hj*4+g. grid(32), 256 thr; block covers 64 cols' (16 hidden units).
// Thread (tx=tid&15, ty=tid>>4): cols tx*4..+3 (one hj, all 4 gates), rows ty*2, ty*2+1.
__global__ void lstm_step_kernel(const float* __restrict__ xpI, const float* __restrict__ whhI,
                                 const float* __restrict__ h_in, const float* __restrict__ c_in,
                                 float* __restrict__ h_out, float* __restrict__ c_out,
                                 float* __restrict__ hs, int t) {
    __shared__ float hsm[64][33];     // [k][b]
    __shared__ float wsm[64][64];     // [k][c_local]
    int tid = threadIdx.x;
    int col0 = blockIdx.x * 64;
    int tx = tid & 15, ty = tid >> 4;
    float acc[2][4] = {};
    for (int k0 = 0; k0 < HID; k0 += 64) {
        {
            int b = tid >> 3, kl = (tid & 7) * 8;
            float4 v0 = *(const float4*)(h_in + b*HID + k0 + kl);
            float4 v1 = *(const float4*)(h_in + b*HID + k0 + kl + 4);
            hsm[kl  ][b] = v0.x; hsm[kl+1][b] = v0.y; hsm[kl+2][b] = v0.z; hsm[kl+3][b] = v0.w;
            hsm[kl+4][b] = v1.x; hsm[kl+5][b] = v1.y; hsm[kl+6][b] = v1.z; hsm[kl+7][b] = v1.w;
        }
        for (int i = tid; i < 64*16; i += 256) {
            int k = i >> 4, c4 = (i & 15) * 4;
            *(float4*)&wsm[k][c4] = *(const float4*)(whhI + (long)(k0 + k)*2048 + col0 + c4);
        }
        __syncthreads();
        #pragma unroll 8
        for (int k = 0; k < 64; k++) {
            float4 wv = *(const float4*)&wsm[k][tx*4];
            float h0v = hsm[k][ty*2], h1v = hsm[k][ty*2 + 1];
            acc[0][0] += h0v*wv.x; acc[0][1] += h0v*wv.y;
            acc[0][2] += h0v*wv.z; acc[0][3] += h0v*wv.w;
            acc[1][0] += h1v*wv.x; acc[1][1] += h1v*wv.y;
            acc[1][2] += h1v*wv.z; acc[1][3] += h1v*wv.w;
        }
        __syncthreads();
    }
    int hj = (col0 >> 2) + tx;
    #pragma unroll
    for (int r = 0; r < 2; r++) {
        int b = ty*2 + r;
        const float* xp = xpI + ((long)(b*TS + t))*2048 + col0 + tx*4;
        float gi = acc[r][0] + xp[0];
        float gf = acc[r][1] + xp[1];
        float gg = acc[r][2] + xp[2];
        float go = acc[r][3] + xp[3];
        float si = 1.f/(1.f + expf(-gi));
        float sf = 1.f/(1.f + expf(-gf));
        float tg = tanhf(gg);
        float so = 1.f/(1.f + expf(-go));
        float cn = sf * c_in[b*HID + hj] + si * tg;
        float hn = so * tanhf(cn);
        c_out[b*HID + hj] = cn;
        h_out[b*HID + hj] = hn;
        hs[((long)(b*TS + t))*HID + hj] = hn;
    }
}

// ---------------- host launch ----------------
extern "C" void kernel_launch(void* const* d_in, const int* in_sizes, int n_in,
                              void* d_out, int out_size) {
    const float* images   = (const float*)d_in[0];
    const int*   captions = (const int*)  d_in[1];
    const float* w1  = (const float*)d_in[2];
    const float* g1  = (const float*)d_in[3];
    const float* be1 = (const float*)d_in[4];
    const float* w2  = (const float*)d_in[5];
    const float* g2  = (const float*)d_in[6];
    const float* be2 = (const float*)d_in[7];
    const float* w3  = (const float*)d_in[8];
    const float* g3  = (const float*)d_in[9];
    const float* be3 = (const float*)d_in[10];
    const float* w4  = (const float*)d_in[11];
    const float* g4  = (const float*)d_in[12];
    const float* be4 = (const float*)d_in[13];
    const float* pw  = (const float*)d_in[14];
    const float* pb  = (const float*)d_in[15];
    const float* emb = (const float*)d_in[16];
    const float* ihw = (const float*)d_in[17];
    const float* ihb = (const float*)d_in[18];
    const float* icw = (const float*)d_in[19];
    const float* icb = (const float*)d_in[20];
    const float* wih = (const float*)d_in[21];
    const float* whh = (const float*)d_in[22];
    const float* bih = (const float*)d_in[23];
    const float* bhh = (const float*)d_in[24];
    const float* ow  = (const float*)d_in[25];
    const float* ob  = (const float*)d_in[26];
    float* out = (float*)d_out;

    float *act1, *pool1, *act2, *act3, *act4, *w1p, *part1, *part2, *bna, *bnb;
    float *feats, *enc, *xs, *xpart, *wihI, *whhI, *bI, *hs, *h0, *h1, *c0, *c1;
    cudaGetSymbolAddress((void**)&act1,  g_act1);
    cudaGetSymbolAddress((void**)&pool1, g_pool1);
    cudaGetSymbolAddress((void**)&act2,  g_act2);
    cudaGetSymbolAddress((void**)&act3,  g_act3);
    cudaGetSymbolAddress((void**)&act4,  g_act4);
    cudaGetSymbolAddress((void**)&w1p,   g_w1p);
    cudaGetSymbolAddress((void**)&part1, g_part1);
    cudaGetSymbolAddress((void**)&part2, g_part2);
    cudaGetSymbolAddress((void**)&bna,   g_bna);
    cudaGetSymbolAddress((void**)&bnb,   g_bnb);
    cudaGetSymbolAddress((void**)&feats, g_feats);
    cudaGetSymbolAddress((void**)&enc,   g_enc);
    cudaGetSymbolAddress((void**)&xs,    g_xs);
    cudaGetSymbolAddress((void**)&xpart, g_xpart);
    cudaGetSymbolAddress((void**)&wihI,  g_wihI);
    cudaGetSymbolAddress((void**)&whhI,  g_whhI);
    cudaGetSymbolAddress((void**)&bI,    g_bI);
    cudaGetSymbolAddress((void**)&hs,    g_hs);
    cudaGetSymbolAddress((void**)&h0,    g_h);
    cudaGetSymbolAddress((void**)&c0,    g_c);
    h1 = h0 + BB*HID;
    c1 = c0 + BB*HID;

    // ===== conv1: implicit-GEMM =====
    padw1_kernel<<<40, 256>>>(w1, w1p);
    iconv7_kernel<<<401408/128, 256>>>(w1p, images, act1);
    bn_stats_part_kernel<<<dim3(64, 32), 256>>>(act1, part1, part2, 32, 64, 12544, 32);
    bn_finalize_kernel<<<1, 256>>>(part1, part2, g1, be1, bna, bnb, 64, 32, 1.f/(32.f*12544.f));
    maxpool_bn_kernel<<<(32*64*56*56 + 255)/256, 256>>>(act1, pool1, bna, bnb);

    // ===== conv2: implicit-GEMM (input pool1 already activated) =====
    iconv3_kernel<<<dim3(196, 1), 256>>>(w2, pool1, nullptr, nullptr, act2,
                                         64, 56, 28, 784, 25088, 128);
    bn_stats_part_kernel<<<dim3(128, 32), 256>>>(act2, part1, part2, 32, 128, 784, 32);
    bn_finalize_kernel<<<1, 256>>>(part1, part2, g2, be2, bna, bnb, 128, 32, 1.f/(32.f*784.f));

    // ===== conv3: implicit-GEMM, fused bn2+relu =====
    iconv3_kernel<<<dim3(49, 2), 256>>>(w3, act2, bna, bnb, act3,
                                        128, 28, 14, 196, 6272, 256);
    bn_stats_part_kernel<<<dim3(256, 16), 256>>>(act3, part1, part2, 32, 256, 196, 16);
    bn_finalize_kernel<<<1, 256>>>(part1, part2, g3, be3, bna, bnb, 256, 16, 1.f/(32.f*196.f));

    // ===== conv4: implicit-GEMM, fused bn3+relu (13 col tiles cover 1568) =====
    iconv3_kernel<<<dim3(13, 4), 256>>>(w4, act3, bna, bnb, act4,
                                        256, 14, 7, 49, 1568, 512);
    bn_stats_part_kernel<<<dim3(512, 8), 256>>>(act4, part1, part2, 32, 512, 49, 8);
    bn_finalize_kernel<<<2, 256>>>(part1, part2, g4, be4, bna, bnb, 512, 8, 1.f/(32.f*49.f));

    // ===== fused bn4+relu+avgpool =====
    avgpool_bn_kernel<<<64, 256>>>(act4, feats, bna, bnb);

    // ===== encoder -> LSTM init =====
    fc_kernel<<<64, 256>>>(feats, pw, pb, enc, BB, EMB, 512, 0);
    fc_kernel<<<64, 256>>>(enc, ihw, ihb, h0, BB, HID, EMB, 1);
    fc_kernel<<<64, 256>>>(enc, icw, icb, c0, BB, HID, EMB, 1);

    // ===== interleaved weight transposes + bias =====
    itrans_kernel<<<(512*2048 + 255)/256, 256>>>(wih, wihI, 512);
    itrans_kernel<<<(512*2048 + 255)/256, 256>>>(whh, whhI, 512);
    ibias_kernel<<<8, 256>>>(bih, bhh, bI);

    // ===== embedding + input projection (interleaved, biases folded) =====
    embed_kernel<<<(BB*TS*EMB + 255)/256, 256>>>(captions, emb, xs);
    sgemm128_kernel<<<dim3(2048/128, 640/128), 256>>>(xs, wihI, bI, nullptr, xpart, 640, 2048, 512);

    // ===== LSTM scan (32 blocks/step, interleaved gates) =====
    float* hbuf[2] = { h0, h1 };
    float* cbuf[2] = { c0, c1 };
    for (int t = 0; t < TS; t++) {
        lstm_step_kernel<<<32, 256>>>(xpart, whhI,
                                      hbuf[t & 1], cbuf[t & 1],
                                      hbuf[(t+1) & 1], cbuf[(t+1) & 1],
                                      hs, t);
    }

    // ===== output projection: tf32 tensor cores =====
    tf32gemm_kernel<<<dim3(32000/128, 640/128), 256>>>(hs, ow, ob, out, 640, 32000, 512);
}